// round 13
// baseline (speedup 1.0000x reference)
#include <cuda_runtime.h>
#include <math.h>

#define NB 16
#define NN 2048
#define WC 64
#define NR 4
#define NI 512
#define DELTAF 1e-6f
#define TI 128

// ---- output offsets (flattened tuple order) ----
#define OFF_RV    0
#define OFF_MEM   (NB*NR*WC)                 // 4096
#define OFF_LINK  (OFF_MEM + NB*NN*WC)       // 2101248
#define OFF_PREC  (OFF_LINK + NB*NN*NN)      // 69210112
#define OFF_RW    (OFF_PREC + NB*NN)         // 69242880
#define OFF_WW    (OFF_RW + NB*NR*NN)        // 69373952
#define OFF_USAGE (OFF_WW + NB*NN)           // 69406720

// ---- device scratch ----
__device__ float g_readkeys[NB*NR*WC];
__device__ float g_rs[NB*NR];
__device__ float g_wkey[NB*WC];
__device__ float g_wstr[NB];
__device__ float g_ev[NB*WC];
__device__ float g_wv[NB*WC];
__device__ float g_fg[NB*NR];
__device__ float g_ag[NB];
__device__ float g_wg[NB];
__device__ float g_rmraw[NB*12];
__device__ float g_wcwlog[NB*NN];   // exp(logit) values
__device__ float g_wcwsum[NB];      // per-batch sum of exp
__device__ float g_allocsum[NB];    // per-batch sum of alloc
__device__ float g_alloc[NB*NN];
__device__ float g_fwd[NB*NR*NN];   // direct stores
__device__ float g_bwd[NB*NR*NN];   // atomic accumulated
__device__ float g_rcw[NB*NR*NN];   // logits -> softmaxed in place

struct CP { const float* W[10]; const float* bvec[10]; };

// shuffle butterfly (redux.f32 does NOT exist on sm_103 — verified R11)
__device__ __forceinline__ float warp_sum(float v){
    #pragma unroll
    for (int off = 1; off < 32; off <<= 1) v += __shfl_xor_sync(0xffffffffu, v, off);
    return v;
}

__device__ __forceinline__ float act_apply(int code, float v){
    switch(code){
        case 0: return tanhf(v);
        case 1: return fmaxf(v, 0.f) + log1pf(expf(-fabsf(v)));  // softplus
        case 2: return 1.f/(1.f + expf(-v));                      // sigmoid
        default: return v;
    }
}

__device__ __forceinline__ float* seg_out(int seg){
    switch(seg){
        case 0: return g_readkeys;
        case 1: return g_rs;
        case 2: return g_wkey;
        case 3: return g_wstr;
        case 4: return g_ev;
        case 5: return g_wv;
        case 6: return g_fg;
        case 7: return g_ag;
        case 8: return g_wg;
        default: return g_rmraw;
    }
}

// ---- controller projections: one warp per output row (471 rows) ----
__global__ void k_ctrl(const float* __restrict__ x, CP cp){
    __shared__ float sx[NB*NI];
    int tid = threadIdx.x;
    if (blockIdx.x == 0 && tid < NB) g_wcwsum[tid] = 0.f;   // zero before wcwlog atomics
    for (int i = tid; i < NB*NI; i += blockDim.x) sx[i] = x[i];
    __syncthreads();
    int gw = (blockIdx.x*blockDim.x + tid) >> 5;
    int lane = tid & 31;
    if (gw >= 471) return;
    const int segStart[10] = {0,256,260,324,325,389,453,457,458,459};
    const int segLen[10]   = {256,4,64,1,64,64,4,1,1,12};
    const int segAct[10]   = {0,1,0,1,2,0,2,2,2,3};
    int seg = 0;
    for (int s = 9; s >= 0; s--){ if (gw >= segStart[s]){ seg = s; break; } }
    int rl = gw - segStart[seg];
    const float* W = cp.W[seg] + rl*NI;
    float wreg[16];
    #pragma unroll
    for (int s = 0; s < 16; s++) wreg[s] = W[s*32 + lane];
    float bias = cp.bvec[seg][rl];
    float* outp = seg_out(seg);
    int sl = segLen[seg], ac = segAct[seg];
    for (int b = 0; b < NB; b++){
        const float* xb = &sx[b*NI];
        float sum = 0.f;
        #pragma unroll
        for (int s = 0; s < 16; s++) sum += wreg[s]*xb[s*32 + lane];
        sum = warp_sum(sum);
        if (lane == 0) outp[b*sl + rl] = act_apply(ac, sum + bias);
    }
}

// ---- write-content exp(logits) + per-batch sum (+ folded zeroing) ----
__global__ void k_wcwlog(const float* __restrict__ mem, float* __restrict__ out){
    __shared__ float skey[WC];
    __shared__ float rbuf[8];
    int b = blockIdx.x >> 3;
    int c = blockIdx.x & 7;
    int tid = threadIdx.x;
    int lane = tid & 31, wid = tid >> 5;
    // folded zero: 32768 threads cover bwd (131072) + RV (4096)
    {
        int gt = blockIdx.x*256 + tid;
        #pragma unroll
        for (int k = 0; k < 4; k++) g_bwd[k*32768 + gt] = 0.f;
        if (gt < NB*NR*WC) out[OFF_RV + gt] = 0.f;
    }
    if (tid < WC) skey[tid] = g_wkey[b*WC + tid];
    __syncthreads();
    float kn2 = 0.f;
    #pragma unroll
    for (int i = 0; i < WC; i++) kn2 += skey[i]*skey[i];
    float kn = sqrtf(kn2);
    float beta = g_wstr[b];
    int n = c*256 + tid;
    const float4* row = (const float4*)(mem + ((size_t)b*NN + n)*WC);
    float dot = 0.f, sq = 0.f;
    #pragma unroll
    for (int i = 0; i < WC/4; i++){
        float4 m = row[i];
        dot += m.x*skey[4*i] + m.y*skey[4*i+1] + m.z*skey[4*i+2] + m.w*skey[4*i+3];
        sq  += m.x*m.x + m.y*m.y + m.z*m.z + m.w*m.w;
    }
    float e = expf(beta*dot/(kn*sqrtf(sq) + DELTAF));
    g_wcwlog[b*NN + n] = e;
    float s = warp_sum(e);
    if (lane == 0) rbuf[wid] = s;
    __syncthreads();
    if (tid == 0){
        float t = 0.f;
        #pragma unroll
        for (int w = 0; w < 8; w++) t += rbuf[w];
        atomicAdd(&g_wcwsum[b], t);
    }
}

// ---- usage + allocation (free gates inline) + allocsum ----
__global__ void __launch_bounds__(1024)
k_alloc(const float* __restrict__ u0v, const float* __restrict__ wwold,
        const float* __restrict__ rwold, const float* __restrict__ x,
        const float* __restrict__ W_fg, const float* __restrict__ b_fg,
        float* __restrict__ out){
    __shared__ unsigned keys[NN];
    __shared__ float su[NN];
    __shared__ float warptot[32];
    __shared__ float warpoff[32];
    __shared__ float sfg[NR];
    int b = blockIdx.x, tid = threadIdx.x;   // 1024 threads
    int lane = tid & 31, wid = tid >> 5;
    if (wid < NR){
        int r = wid;
        float s = 0.f;
        #pragma unroll
        for (int i = 0; i < 16; i++)
            s += x[b*NI + i*32 + lane]*W_fg[r*NI + i*32 + lane];
        s = warp_sum(s);
        if (lane == 0) sfg[r] = 1.f/(1.f + expf(-(s + b_fg[r])));
    }
    __syncthreads();
    for (int i = tid; i < NN; i += 1024){
        float u0 = u0v[b*NN + i];
        float u = u0 + (1.f - u0)*wwold[b*NN + i];
        float ret = 1.f;
        #pragma unroll
        for (int r = 0; r < NR; r++) ret *= (1.f - sfg[r]*rwold[(b*NR+r)*NN + i]);
        float usage = u*ret;
        out[OFF_USAGE + b*NN + i] = usage;
        float uu = DELTAF + (1.f - DELTAF)*usage;
        su[i] = uu;
        keys[i] = (__float_as_uint(uu) & 0xFFFFF800u) | (unsigned)i;
    }
    __syncthreads();
    for (int k = 2; k <= NN; k <<= 1){
        for (int j = k >> 1; j > 0; j >>= 1){
            #pragma unroll
            for (int h = 0; h < 2; h++){
                int i = h*1024 + tid;
                int ixj = i ^ j;
                if (ixj > i){
                    bool up = ((i & k) == 0);
                    unsigned a = keys[i], c = keys[ixj];
                    if (up ? (a > c) : (a < c)){ keys[i] = c; keys[ixj] = a; }
                }
            }
            if (j >= 32) __syncthreads(); else __syncwarp();
        }
        if (k >= 32) __syncthreads();
    }
    __syncthreads();
    unsigned k0 = keys[2*tid], k1 = keys[2*tid + 1];
    float u0s = su[k0 & 0x7FFu];
    float u1s = su[k1 & 0x7FFu];
    float incl = u0s*u1s;
    #pragma unroll
    for (int d = 1; d < 32; d <<= 1){
        float v = __shfl_up_sync(0xffffffffu, incl, d);
        if (lane >= d) incl *= v;
    }
    if (lane == 31) warptot[wid] = incl;
    __syncthreads();
    if (wid == 0){
        float winc = warptot[lane];
        #pragma unroll
        for (int d = 1; d < 32; d <<= 1){
            float v = __shfl_up_sync(0xffffffffu, winc, d);
            if (lane >= d) winc *= v;
        }
        float wex = __shfl_up_sync(0xffffffffu, winc, 1);
        if (lane == 0) wex = 1.f;
        warpoff[lane] = wex;
    }
    __syncthreads();
    float excl = __shfl_up_sync(0xffffffffu, incl, 1);
    if (lane == 0) excl = 1.f;
    float pre0 = warpoff[wid]*excl;
    float pre1 = pre0*u0s;
    float a0 = (1.f - u0s)*pre0;
    float a1 = (1.f - u1s)*pre1;
    g_alloc[b*NN + (k0 & 0x7FFu)] = a0;
    g_alloc[b*NN + (k1 & 0x7FFu)] = a1;
    float asum = warp_sum(a0 + a1);
    __syncthreads();
    if (lane == 0) warptot[wid] = asum;
    __syncthreads();
    if (tid == 0){
        float t = 0.f;
        #pragma unroll
        for (int w = 0; w < 32; w++) t += warptot[w];
        g_allocsum[b] = t;
    }
}

// ---- ww + precedence outputs (side stream; not on critical path) ----
__global__ void k_ww(const float* __restrict__ prec_old, float* __restrict__ out){
    int b = blockIdx.x >> 3;
    int n = (blockIdx.x & 7)*256 + threadIdx.x;
    float inv = 1.f/g_wcwsum[b];
    float agv = g_ag[b], wgv = g_wg[b];
    float S = wgv*(agv*g_allocsum[b] + (1.f - agv));
    float w = wgv*(agv*g_alloc[b*NN+n] + (1.f-agv)*g_wcwlog[b*NN+n]*inv);
    out[OFF_WW + b*NN + n] = w;
    out[OFF_PREC + b*NN + n] = (1.f - S)*prec_old[b*NN + n] + w;
}

// ---- memory update + read-content logits (fused), one warp per row ----
__global__ void k_memnew(const float* __restrict__ mem, float* __restrict__ out){
    __shared__ float skey[NR*WC];
    __shared__ float sknorm[NR];
    __shared__ float sev[WC], swv[WC];
    int b = blockIdx.x >> 8;
    int rowblk = blockIdx.x & 255;
    int tid = threadIdx.x;
    skey[tid] = g_readkeys[b*NR*WC + tid];
    if (tid < WC){ sev[tid] = g_ev[b*WC + tid]; swv[tid] = g_wv[b*WC + tid]; }
    __syncthreads();
    if (tid < NR){
        float s = 0.f;
        #pragma unroll
        for (int i = 0; i < WC; i++){ float v = skey[tid*WC + i]; s += v*v; }
        sknorm[tid] = sqrtf(s);
    }
    __syncthreads();
    int wrp = tid >> 5, lane = tid & 31;
    int n = rowblk*8 + wrp;
    int row = b*NN + n;
    int w0 = lane*2;
    float2 m = *(const float2*)(mem + (size_t)row*WC + w0);
    float ww = out[OFF_WW + row];
    float n0 = m.x*(1.f - ww*sev[w0])   + ww*swv[w0];
    float n1 = m.y*(1.f - ww*sev[w0+1]) + ww*swv[w0+1];
    *(float2*)(out + OFF_MEM + (size_t)row*WC + w0) = make_float2(n0, n1);
    float d[NR], sq = warp_sum(n0*n0 + n1*n1);
    #pragma unroll
    for (int r = 0; r < NR; r++)
        d[r] = warp_sum(n0*skey[r*WC + w0] + n1*skey[r*WC + w0 + 1]);
    if (lane == 0){
        float mn = sqrtf(sq);
        #pragma unroll
        for (int r = 0; r < NR; r++)
            g_rcw[(b*NR+r)*NN + n] = g_rs[b*NR+r]*d[r]/(sknorm[r]*mn + DELTAF);
    }
}

// ---- read-content softmax (in place), one block per (b,r) ----
__global__ void k_rcwsm(){
    __shared__ float sl[NN];
    __shared__ float rbuf[256];
    int base = blockIdx.x*NN;
    int tid = threadIdx.x;
    float mx = -1e30f;
    #pragma unroll
    for (int k = 0; k < 8; k++){
        float v = g_rcw[base + k*256 + tid];
        sl[k*256 + tid] = v;
        mx = fmaxf(mx, v);
    }
    rbuf[tid] = mx; __syncthreads();
    for (int s = 128; s; s >>= 1){ if (tid < s) rbuf[tid] = fmaxf(rbuf[tid], rbuf[tid+s]); __syncthreads(); }
    mx = rbuf[0]; __syncthreads();
    float sum = 0.f;
    #pragma unroll
    for (int k = 0; k < 8; k++){
        float e = expf(sl[k*256 + tid] - mx);
        sl[k*256 + tid] = e; sum += e;
    }
    rbuf[tid] = sum; __syncthreads();
    for (int s = 128; s; s >>= 1){ if (tid < s) rbuf[tid] += rbuf[tid+s]; __syncthreads(); }
    float inv = 1.f/rbuf[0];
    #pragma unroll
    for (int k = 0; k < 8; k++) g_rcw[base + k*256 + tid] = sl[k*256 + tid]*inv;
}

// ---- fused link update + fwd/bwd: 512 threads, 4 j-cols/thread,
//      2-row batching + software-pipelined (double-buffered) loads ----
__global__ void __launch_bounds__(512, 2)
k_link(const float* __restrict__ link_old, const float* __restrict__ prec_old,
       const float* __restrict__ rw_old, float* __restrict__ out){
    __shared__ float wwi_s[TI];
    __shared__ float rwi_s[NR][TI];
    __shared__ float sfwd[TI][NR][17];   // 16 warp-partials + pad
    __shared__ float cfix[TI][NR];       // diag corrections for fwd
    int b = blockIdx.y;
    int i0 = blockIdx.x * TI;
    int tid = threadIdx.x;
    int wrp = tid >> 5, lane = tid & 31;
    float inv = 1.f/g_wcwsum[b];
    float agv = g_ag[b], wgv = g_wg[b];
    float c_alloc = wgv*agv;
    float c_cw = wgv*(1.f-agv)*inv;
    if (tid < TI)
        wwi_s[tid] = c_alloc*g_alloc[b*NN + i0 + tid] + c_cw*g_wcwlog[b*NN + i0 + tid];
    {   // 512 threads load 512 rwi values
        int r = tid >> 7, ii = tid & 127;
        rwi_s[r][ii] = rw_old[(b*NR+r)*NN + i0 + ii];
    }
    int jb = tid * 4;
    float wwj[4], pj[4], rwj[NR][4];
    #pragma unroll
    for (int k = 0; k < 4; k++){
        wwj[k] = c_alloc*g_alloc[b*NN + jb + k] + c_cw*g_wcwlog[b*NN + jb + k];
        pj[k]  = prec_old[b*NN + jb + k];
    }
    #pragma unroll
    for (int r = 0; r < NR; r++)
        #pragma unroll
        for (int k = 0; k < 4; k++) rwj[r][k] = rw_old[(b*NR+r)*NN + jb + k];
    float bwd[NR][4];
    #pragma unroll
    for (int r = 0; r < NR; r++)
        #pragma unroll
        for (int k = 0; k < 4; k++) bwd[r][k] = 0.f;
    __syncthreads();
    const float* Lb = link_old + ((size_t)b*NN + i0)*NN + jb;
    float* Ob = out + OFF_LINK + ((size_t)b*NN + i0)*NN + jb;
    // prologue loads for rows 0,1
    float4 oA = __ldcs((const float4*)(Lb));
    float4 oB = __ldcs((const float4*)(Lb + NN));
    #pragma unroll 1
    for (int ii0 = 0; ii0 < TI; ii0 += 2){
        // prefetch next pair while computing current (MLP across iterations)
        float4 nAo = oA, nBo = oB;
        if (ii0 + 2 < TI){
            nAo = __ldcs((const float4*)(Lb + (size_t)(ii0+2)*NN));
            nBo = __ldcs((const float4*)(Lb + (size_t)(ii0+3)*NN));
        }
        float wwiA = wwi_s[ii0],   t1A = 1.f - wwiA;
        float wwiB = wwi_s[ii0+1], t1B = 1.f - wwiB;
        float nvA[4], nvB[4];
        nvA[0] = (t1A - wwj[0])*oA.x + wwiA*pj[0];
        nvA[1] = (t1A - wwj[1])*oA.y + wwiA*pj[1];
        nvA[2] = (t1A - wwj[2])*oA.z + wwiA*pj[2];
        nvA[3] = (t1A - wwj[3])*oA.w + wwiA*pj[3];
        nvB[0] = (t1B - wwj[0])*oB.x + wwiB*pj[0];
        nvB[1] = (t1B - wwj[1])*oB.y + wwiB*pj[1];
        nvB[2] = (t1B - wwj[2])*oB.z + wwiB*pj[2];
        nvB[3] = (t1B - wwj[3])*oB.w + wwiB*pj[3];
        __stcs((float4*)(Ob + (size_t)ii0*NN),     make_float4(nvA[0],nvA[1],nvA[2],nvA[3]));
        __stcs((float4*)(Ob + (size_t)(ii0+1)*NN), make_float4(nvB[0],nvB[1],nvB[2],nvB[3]));
        // 8 reduction values, butterflies interleaved (independent chains)
        float fA[NR], fB[NR];
        #pragma unroll
        for (int r = 0; r < NR; r++){
            fA[r] = nvA[0]*rwj[r][0] + nvA[1]*rwj[r][1] + nvA[2]*rwj[r][2] + nvA[3]*rwj[r][3];
            fB[r] = nvB[0]*rwj[r][0] + nvB[1]*rwj[r][1] + nvB[2]*rwj[r][2] + nvB[3]*rwj[r][3];
        }
        #pragma unroll
        for (int off = 1; off < 32; off <<= 1){
            #pragma unroll
            for (int r = 0; r < NR; r++){
                fA[r] += __shfl_xor_sync(0xffffffffu, fA[r], off);
                fB[r] += __shfl_xor_sync(0xffffffffu, fB[r], off);
            }
        }
        if (lane == 0){
            #pragma unroll
            for (int r = 0; r < NR; r++){
                sfwd[ii0][r][wrp]   = fA[r];
                sfwd[ii0+1][r][wrp] = fB[r];
            }
        }
        #pragma unroll
        for (int r = 0; r < NR; r++){
            float rwiA = rwi_s[r][ii0], rwiB = rwi_s[r][ii0+1];
            #pragma unroll
            for (int k = 0; k < 4; k++) bwd[r][k] += rwiA*nvA[k] + rwiB*nvB[k];
        }
        oA = nAo; oB = nBo;
    }
    // diag fix: 32 threads own the block's 128 diagonal elements
    if (jb >= i0 && jb < i0 + TI){
        #pragma unroll
        for (int k = 0; k < 4; k++){
            int ii = jb - i0 + k;               // row; column jb+k == i0+ii
            float wwi = wwi_s[ii];
            float oldd = Lb[(size_t)ii*NN + k];
            float v = (1.f - wwi - wwj[k])*oldd + wwi*pj[k];
            Ob[(size_t)ii*NN + k] = 0.f;
            #pragma unroll
            for (int r = 0; r < NR; r++){
                bwd[r][k] -= rwi_s[r][ii]*v;
                cfix[ii][r] = v*rwj[r][k];
            }
        }
    }
    __syncthreads();
    {   // fwd reduce: 512 outputs (TI*NR), one per thread
        int ii = tid >> 2, r = tid & 3;
        float s = -cfix[ii][r];
        #pragma unroll
        for (int w = 0; w < 16; w++) s += sfwd[ii][r][w];
        g_fwd[(b*NR+r)*NN + i0 + ii] = s;
    }
    #pragma unroll
    for (int r = 0; r < NR; r++)
        #pragma unroll
        for (int k = 0; k < 4; k++) atomicAdd(&g_bwd[(b*NR+r)*NN + jb + k], bwd[r][k]);
}

// ---- rw_new mix + read vectors (partial over 64-n chunks, atomics into out) ----
__global__ void k_rvrw(float* __restrict__ out){
    __shared__ float tile[64*WC];
    __shared__ float srw[NR*64];
    int b = blockIdx.x >> 5;
    int c = blockIdx.x & 31;
    int tid = threadIdx.x;
    int r = tid >> 6, idx = tid & 63;
    int n0 = c*64, n = n0 + idx;
    float m0r = g_rmraw[b*12 + r*3 + 0];
    float m1r = g_rmraw[b*12 + r*3 + 1];
    float m2r = g_rmraw[b*12 + r*3 + 2];
    float mx = fmaxf(m0r, fmaxf(m1r, m2r));
    float e0 = expf(m0r-mx), e1 = expf(m1r-mx), e2 = expf(m2r-mx);
    float inv = 1.f/(e0+e1+e2);
    int base = (b*NR+r)*NN;
    float rwv = e0*inv*g_bwd[base+n] + e1*inv*g_fwd[base+n] + e2*inv*g_rcw[base+n];
    out[OFF_RW + base + n] = rwv;
    srw[r*64 + idx] = rwv;
    for (int i = tid; i < 64*WC; i += 256)
        tile[i] = out[OFF_MEM + ((size_t)b*NN + n0)*WC + i];
    __syncthreads();
    float acc = 0.f;
    #pragma unroll 8
    for (int i = 0; i < 64; i++) acc += srw[r*64 + i]*tile[i*WC + idx];
    atomicAdd(&out[OFF_RV + b*256 + r*64 + idx], acc);
}

extern "C" void kernel_launch(void* const* d_in, const int* in_sizes, int n_in,
                              void* d_out, int out_size){
    const float* x        = (const float*)d_in[0];
    const float* memory   = (const float*)d_in[1];
    const float* link_old = (const float*)d_in[2];
    const float* prec     = (const float*)d_in[3];
    const float* rw_old   = (const float*)d_in[4];
    const float* ww_old   = (const float*)d_in[5];
    const float* usage0   = (const float*)d_in[6];
    CP cp;
    for (int s = 0; s < 10; s++){
        cp.W[s]    = (const float*)d_in[7 + 2*s];
        cp.bvec[s] = (const float*)d_in[8 + 2*s];
    }
    const float* W_fg = cp.W[6];
    const float* b_fg = cp.bvec[6];
    float* out = (float*)d_out;

    static cudaStream_t s1 = nullptr;
    static cudaEvent_t eF = nullptr, eA = nullptr, e1 = nullptr, e2 = nullptr;
    if (!s1){
        cudaStreamCreateWithFlags(&s1, cudaStreamNonBlocking);
        cudaEventCreateWithFlags(&eF, cudaEventDisableTiming);
        cudaEventCreateWithFlags(&eA, cudaEventDisableTiming);
        cudaEventCreateWithFlags(&e1, cudaEventDisableTiming);
        cudaEventCreateWithFlags(&e2, cudaEventDisableTiming);
    }

    // FORK: side stream joins capture via event before any launch on it.
    cudaEventRecord(eF, 0);
    cudaStreamWaitEvent(s1, eF, 0);

    // main: alloc -> [join e1] -> link(inline ww) -> [join e2] -> rvrw
    // side: ctrl -> wcwlog(+zero) -> (e1) -> [wait eA] -> ww -> memnew -> rcwsm -> (e2)
    k_alloc <<<NB, 1024>>>(usage0, ww_old, rw_old, x, W_fg, b_fg, out);  // main
    cudaEventRecord(eA, 0);

    k_ctrl  <<<59, 256, 0, s1>>>(x, cp);                                 // side
    k_wcwlog<<<NB*8, 256, 0, s1>>>(memory, out);                         // side
    cudaEventRecord(e1, s1);
    cudaStreamWaitEvent(s1, eA, 0);

    cudaStreamWaitEvent(0, e1, 0);
    k_link  <<<dim3(NN/TI, NB), 512>>>(link_old, prec, rw_old, out);     // main (big)

    k_ww    <<<NB*8, 256, 0, s1>>>(prec, out);                           // side
    k_memnew<<<NB*256, 256, 0, s1>>>(memory, out);                       // side
    k_rcwsm <<<NB*NR, 256, 0, s1>>>();                                   // side
    cudaEventRecord(e2, s1);
    cudaStreamWaitEvent(0, e2, 0);

    k_rvrw  <<<NB*32, 256>>>(out);                                       // main
}

// round 14
// speedup vs baseline: 1.0194x; 1.0194x over previous
#include <cuda_runtime.h>
#include <math.h>

#define NB 16
#define NN 2048
#define WC 64
#define NR 4
#define NI 512
#define DELTAF 1e-6f
#define TI 128

// ---- output offsets (flattened tuple order) ----
#define OFF_RV    0
#define OFF_MEM   (NB*NR*WC)                 // 4096
#define OFF_LINK  (OFF_MEM + NB*NN*WC)       // 2101248
#define OFF_PREC  (OFF_LINK + NB*NN*NN)      // 69210112
#define OFF_RW    (OFF_PREC + NB*NN)         // 69242880
#define OFF_WW    (OFF_RW + NB*NR*NN)        // 69373952
#define OFF_USAGE (OFF_WW + NB*NN)           // 69406720

// ---- device scratch ----
__device__ float g_readkeys[NB*NR*WC];
__device__ float g_rs[NB*NR];
__device__ float g_wkey[NB*WC];
__device__ float g_wstr[NB];
__device__ float g_ev[NB*WC];
__device__ float g_wv[NB*WC];
__device__ float g_fg[NB*NR];
__device__ float g_ag[NB];
__device__ float g_wg[NB];
__device__ float g_rmraw[NB*12];
__device__ float g_wcwlog[NB*NN];   // exp(logit) values
__device__ float g_wcwsum[NB];      // per-batch sum of exp
__device__ float g_allocsum[NB];    // per-batch sum of alloc
__device__ float g_alloc[NB*NN];
__device__ float g_fwd[NB*NR*NN];   // direct stores
__device__ float g_bwd[NB*NR*NN];   // atomic accumulated
__device__ float g_rcw[NB*NR*NN];   // logits -> softmaxed in place

struct CP { const float* W[10]; const float* bvec[10]; };

// shuffle butterfly (redux.f32 does NOT exist on sm_103 — verified R11)
__device__ __forceinline__ float warp_sum(float v){
    #pragma unroll
    for (int off = 1; off < 32; off <<= 1) v += __shfl_xor_sync(0xffffffffu, v, off);
    return v;
}

// packed f32x2 add (FFMA2-class; PTX-only on sm_103)
__device__ __forceinline__ void add_f32x2(float& a, float& b, float ta, float tb){
    unsigned long long pa, pt, po;
    asm("mov.b64 %0, {%1, %2};" : "=l"(pa) : "f"(a), "f"(b));
    asm("mov.b64 %0, {%1, %2};" : "=l"(pt) : "f"(ta), "f"(tb));
    asm("add.rn.f32x2 %0, %1, %2;" : "=l"(po) : "l"(pa), "l"(pt));
    asm("mov.b64 {%0, %1}, %2;" : "=f"(a), "=f"(b) : "l"(po));
}

__device__ __forceinline__ float act_apply(int code, float v){
    switch(code){
        case 0: return tanhf(v);
        case 1: return fmaxf(v, 0.f) + log1pf(expf(-fabsf(v)));  // softplus
        case 2: return 1.f/(1.f + expf(-v));                      // sigmoid
        default: return v;
    }
}

__device__ __forceinline__ float* seg_out(int seg){
    switch(seg){
        case 0: return g_readkeys;
        case 1: return g_rs;
        case 2: return g_wkey;
        case 3: return g_wstr;
        case 4: return g_ev;
        case 5: return g_wv;
        case 6: return g_fg;
        case 7: return g_ag;
        case 8: return g_wg;
        default: return g_rmraw;
    }
}

// ---- controller projections: one warp per output row (471 rows) ----
__global__ void k_ctrl(const float* __restrict__ x, CP cp){
    __shared__ float sx[NB*NI];
    int tid = threadIdx.x;
    if (blockIdx.x == 0 && tid < NB) g_wcwsum[tid] = 0.f;   // zero before wcwlog atomics
    for (int i = tid; i < NB*NI; i += blockDim.x) sx[i] = x[i];
    __syncthreads();
    int gw = (blockIdx.x*blockDim.x + tid) >> 5;
    int lane = tid & 31;
    if (gw >= 471) return;
    const int segStart[10] = {0,256,260,324,325,389,453,457,458,459};
    const int segLen[10]   = {256,4,64,1,64,64,4,1,1,12};
    const int segAct[10]   = {0,1,0,1,2,0,2,2,2,3};
    int seg = 0;
    for (int s = 9; s >= 0; s--){ if (gw >= segStart[s]){ seg = s; break; } }
    int rl = gw - segStart[seg];
    const float* W = cp.W[seg] + rl*NI;
    float wreg[16];
    #pragma unroll
    for (int s = 0; s < 16; s++) wreg[s] = W[s*32 + lane];
    float bias = cp.bvec[seg][rl];
    float* outp = seg_out(seg);
    int sl = segLen[seg], ac = segAct[seg];
    for (int b = 0; b < NB; b++){
        const float* xb = &sx[b*NI];
        float sum = 0.f;
        #pragma unroll
        for (int s = 0; s < 16; s++) sum += wreg[s]*xb[s*32 + lane];
        sum = warp_sum(sum);
        if (lane == 0) outp[b*sl + rl] = act_apply(ac, sum + bias);
    }
}

// ---- write-content exp(logits) + per-batch sum (+ folded zeroing) ----
__global__ void k_wcwlog(const float* __restrict__ mem, float* __restrict__ out){
    __shared__ float skey[WC];
    __shared__ float rbuf[8];
    int b = blockIdx.x >> 3;
    int c = blockIdx.x & 7;
    int tid = threadIdx.x;
    int lane = tid & 31, wid = tid >> 5;
    // folded zero: 32768 threads cover bwd (131072) + RV (4096)
    {
        int gt = blockIdx.x*256 + tid;
        #pragma unroll
        for (int k = 0; k < 4; k++) g_bwd[k*32768 + gt] = 0.f;
        if (gt < NB*NR*WC) out[OFF_RV + gt] = 0.f;
    }
    if (tid < WC) skey[tid] = g_wkey[b*WC + tid];
    __syncthreads();
    float kn2 = 0.f;
    #pragma unroll
    for (int i = 0; i < WC; i++) kn2 += skey[i]*skey[i];
    float kn = sqrtf(kn2);
    float beta = g_wstr[b];
    int n = c*256 + tid;
    const float4* row = (const float4*)(mem + ((size_t)b*NN + n)*WC);
    float dot = 0.f, sq = 0.f;
    #pragma unroll
    for (int i = 0; i < WC/4; i++){
        float4 m = row[i];
        dot += m.x*skey[4*i] + m.y*skey[4*i+1] + m.z*skey[4*i+2] + m.w*skey[4*i+3];
        sq  += m.x*m.x + m.y*m.y + m.z*m.z + m.w*m.w;
    }
    float e = expf(beta*dot/(kn*sqrtf(sq) + DELTAF));
    g_wcwlog[b*NN + n] = e;
    float s = warp_sum(e);
    if (lane == 0) rbuf[wid] = s;
    __syncthreads();
    if (tid == 0){
        float t = 0.f;
        #pragma unroll
        for (int w = 0; w < 8; w++) t += rbuf[w];
        atomicAdd(&g_wcwsum[b], t);
    }
}

// ---- usage + allocation (free gates inline) + allocsum ----
__global__ void __launch_bounds__(1024)
k_alloc(const float* __restrict__ u0v, const float* __restrict__ wwold,
        const float* __restrict__ rwold, const float* __restrict__ x,
        const float* __restrict__ W_fg, const float* __restrict__ b_fg,
        float* __restrict__ out){
    __shared__ unsigned keys[NN];
    __shared__ float su[NN];
    __shared__ float warptot[32];
    __shared__ float warpoff[32];
    __shared__ float sfg[NR];
    int b = blockIdx.x, tid = threadIdx.x;   // 1024 threads
    int lane = tid & 31, wid = tid >> 5;
    if (wid < NR){
        int r = wid;
        float s = 0.f;
        #pragma unroll
        for (int i = 0; i < 16; i++)
            s += x[b*NI + i*32 + lane]*W_fg[r*NI + i*32 + lane];
        s = warp_sum(s);
        if (lane == 0) sfg[r] = 1.f/(1.f + expf(-(s + b_fg[r])));
    }
    __syncthreads();
    for (int i = tid; i < NN; i += 1024){
        float u0 = u0v[b*NN + i];
        float u = u0 + (1.f - u0)*wwold[b*NN + i];
        float ret = 1.f;
        #pragma unroll
        for (int r = 0; r < NR; r++) ret *= (1.f - sfg[r]*rwold[(b*NR+r)*NN + i]);
        float usage = u*ret;
        out[OFF_USAGE + b*NN + i] = usage;
        float uu = DELTAF + (1.f - DELTAF)*usage;
        su[i] = uu;
        keys[i] = (__float_as_uint(uu) & 0xFFFFF800u) | (unsigned)i;
    }
    __syncthreads();
    for (int k = 2; k <= NN; k <<= 1){
        for (int j = k >> 1; j > 0; j >>= 1){
            #pragma unroll
            for (int h = 0; h < 2; h++){
                int i = h*1024 + tid;
                int ixj = i ^ j;
                if (ixj > i){
                    bool up = ((i & k) == 0);
                    unsigned a = keys[i], c = keys[ixj];
                    if (up ? (a > c) : (a < c)){ keys[i] = c; keys[ixj] = a; }
                }
            }
            if (j >= 32) __syncthreads(); else __syncwarp();
        }
        if (k >= 32) __syncthreads();
    }
    __syncthreads();
    unsigned k0 = keys[2*tid], k1 = keys[2*tid + 1];
    float u0s = su[k0 & 0x7FFu];
    float u1s = su[k1 & 0x7FFu];
    float incl = u0s*u1s;
    #pragma unroll
    for (int d = 1; d < 32; d <<= 1){
        float v = __shfl_up_sync(0xffffffffu, incl, d);
        if (lane >= d) incl *= v;
    }
    if (lane == 31) warptot[wid] = incl;
    __syncthreads();
    if (wid == 0){
        float winc = warptot[lane];
        #pragma unroll
        for (int d = 1; d < 32; d <<= 1){
            float v = __shfl_up_sync(0xffffffffu, winc, d);
            if (lane >= d) winc *= v;
        }
        float wex = __shfl_up_sync(0xffffffffu, winc, 1);
        if (lane == 0) wex = 1.f;
        warpoff[lane] = wex;
    }
    __syncthreads();
    float excl = __shfl_up_sync(0xffffffffu, incl, 1);
    if (lane == 0) excl = 1.f;
    float pre0 = warpoff[wid]*excl;
    float pre1 = pre0*u0s;
    float a0 = (1.f - u0s)*pre0;
    float a1 = (1.f - u1s)*pre1;
    g_alloc[b*NN + (k0 & 0x7FFu)] = a0;
    g_alloc[b*NN + (k1 & 0x7FFu)] = a1;
    float asum = warp_sum(a0 + a1);
    __syncthreads();
    if (lane == 0) warptot[wid] = asum;
    __syncthreads();
    if (tid == 0){
        float t = 0.f;
        #pragma unroll
        for (int w = 0; w < 32; w++) t += warptot[w];
        g_allocsum[b] = t;
    }
}

// ---- ww + precedence outputs (side stream; not on critical path) ----
__global__ void k_ww(const float* __restrict__ prec_old, float* __restrict__ out){
    int b = blockIdx.x >> 3;
    int n = (blockIdx.x & 7)*256 + threadIdx.x;
    float inv = 1.f/g_wcwsum[b];
    float agv = g_ag[b], wgv = g_wg[b];
    float S = wgv*(agv*g_allocsum[b] + (1.f - agv));
    float w = wgv*(agv*g_alloc[b*NN+n] + (1.f-agv)*g_wcwlog[b*NN+n]*inv);
    out[OFF_WW + b*NN + n] = w;
    out[OFF_PREC + b*NN + n] = (1.f - S)*prec_old[b*NN + n] + w;
}

// ---- memory update + read-content logits (fused), one warp per row ----
__global__ void k_memnew(const float* __restrict__ mem, float* __restrict__ out){
    __shared__ float skey[NR*WC];
    __shared__ float sknorm[NR];
    __shared__ float sev[WC], swv[WC];
    int b = blockIdx.x >> 8;
    int rowblk = blockIdx.x & 255;
    int tid = threadIdx.x;
    skey[tid] = g_readkeys[b*NR*WC + tid];
    if (tid < WC){ sev[tid] = g_ev[b*WC + tid]; swv[tid] = g_wv[b*WC + tid]; }
    __syncthreads();
    if (tid < NR){
        float s = 0.f;
        #pragma unroll
        for (int i = 0; i < WC; i++){ float v = skey[tid*WC + i]; s += v*v; }
        sknorm[tid] = sqrtf(s);
    }
    __syncthreads();
    int wrp = tid >> 5, lane = tid & 31;
    int n = rowblk*8 + wrp;
    int row = b*NN + n;
    int w0 = lane*2;
    float2 m = *(const float2*)(mem + (size_t)row*WC + w0);
    float ww = out[OFF_WW + row];
    float n0 = m.x*(1.f - ww*sev[w0])   + ww*swv[w0];
    float n1 = m.y*(1.f - ww*sev[w0+1]) + ww*swv[w0+1];
    *(float2*)(out + OFF_MEM + (size_t)row*WC + w0) = make_float2(n0, n1);
    float d[NR], sq = warp_sum(n0*n0 + n1*n1);
    #pragma unroll
    for (int r = 0; r < NR; r++)
        d[r] = warp_sum(n0*skey[r*WC + w0] + n1*skey[r*WC + w0 + 1]);
    if (lane == 0){
        float mn = sqrtf(sq);
        #pragma unroll
        for (int r = 0; r < NR; r++)
            g_rcw[(b*NR+r)*NN + n] = g_rs[b*NR+r]*d[r]/(sknorm[r]*mn + DELTAF);
    }
}

// ---- read-content softmax (in place), one block per (b,r) ----
__global__ void k_rcwsm(){
    __shared__ float sl[NN];
    __shared__ float rbuf[256];
    int base = blockIdx.x*NN;
    int tid = threadIdx.x;
    float mx = -1e30f;
    #pragma unroll
    for (int k = 0; k < 8; k++){
        float v = g_rcw[base + k*256 + tid];
        sl[k*256 + tid] = v;
        mx = fmaxf(mx, v);
    }
    rbuf[tid] = mx; __syncthreads();
    for (int s = 128; s; s >>= 1){ if (tid < s) rbuf[tid] = fmaxf(rbuf[tid], rbuf[tid+s]); __syncthreads(); }
    mx = rbuf[0]; __syncthreads();
    float sum = 0.f;
    #pragma unroll
    for (int k = 0; k < 8; k++){
        float e = expf(sl[k*256 + tid] - mx);
        sl[k*256 + tid] = e; sum += e;
    }
    rbuf[tid] = sum; __syncthreads();
    for (int s = 128; s; s >>= 1){ if (tid < s) rbuf[tid] += rbuf[tid+s]; __syncthreads(); }
    float inv = 1.f/rbuf[0];
    #pragma unroll
    for (int k = 0; k < 8; k++) g_rcw[base + k*256 + tid] = sl[k*256 + tid]*inv;
}

// ---- fused link update + fwd/bwd: 512 threads, 4 j-cols/thread,
//      2-row batching (R12 shape) + packed f32x2 butterfly adds ----
__global__ void __launch_bounds__(512, 2)
k_link(const float* __restrict__ link_old, const float* __restrict__ prec_old,
       const float* __restrict__ rw_old, float* __restrict__ out){
    __shared__ float wwi_s[TI];
    __shared__ float rwi_s[NR][TI];
    __shared__ float sfwd[TI][NR][17];   // 16 warp-partials + pad
    __shared__ float cfix[TI][NR];       // diag corrections for fwd
    int b = blockIdx.y;
    int i0 = blockIdx.x * TI;
    int tid = threadIdx.x;
    int wrp = tid >> 5, lane = tid & 31;
    float inv = 1.f/g_wcwsum[b];
    float agv = g_ag[b], wgv = g_wg[b];
    float c_alloc = wgv*agv;
    float c_cw = wgv*(1.f-agv)*inv;
    if (tid < TI)
        wwi_s[tid] = c_alloc*g_alloc[b*NN + i0 + tid] + c_cw*g_wcwlog[b*NN + i0 + tid];
    {   // 512 threads load 512 rwi values
        int r = tid >> 7, ii = tid & 127;
        rwi_s[r][ii] = rw_old[(b*NR+r)*NN + i0 + ii];
    }
    int jb = tid * 4;
    float wwj[4], pj[4], rwj[NR][4];
    #pragma unroll
    for (int k = 0; k < 4; k++){
        wwj[k] = c_alloc*g_alloc[b*NN + jb + k] + c_cw*g_wcwlog[b*NN + jb + k];
        pj[k]  = prec_old[b*NN + jb + k];
    }
    #pragma unroll
    for (int r = 0; r < NR; r++)
        #pragma unroll
        for (int k = 0; k < 4; k++) rwj[r][k] = rw_old[(b*NR+r)*NN + jb + k];
    float bwd[NR][4];
    #pragma unroll
    for (int r = 0; r < NR; r++)
        #pragma unroll
        for (int k = 0; k < 4; k++) bwd[r][k] = 0.f;
    __syncthreads();
    const float* Lb = link_old + ((size_t)b*NN + i0)*NN + jb;
    float* Ob = out + OFF_LINK + ((size_t)b*NN + i0)*NN + jb;
    #pragma unroll 2
    for (int ii0 = 0; ii0 < TI; ii0 += 2){
        // both rows' loads issued up front (MLP x2; ptxas batches across unroll)
        float4 oA = __ldcs((const float4*)(Lb + (size_t)ii0*NN));
        float4 oB = __ldcs((const float4*)(Lb + (size_t)(ii0+1)*NN));
        float wwiA = wwi_s[ii0],   t1A = 1.f - wwiA;
        float wwiB = wwi_s[ii0+1], t1B = 1.f - wwiB;
        float nvA[4], nvB[4];
        nvA[0] = (t1A - wwj[0])*oA.x + wwiA*pj[0];
        nvA[1] = (t1A - wwj[1])*oA.y + wwiA*pj[1];
        nvA[2] = (t1A - wwj[2])*oA.z + wwiA*pj[2];
        nvA[3] = (t1A - wwj[3])*oA.w + wwiA*pj[3];
        nvB[0] = (t1B - wwj[0])*oB.x + wwiB*pj[0];
        nvB[1] = (t1B - wwj[1])*oB.y + wwiB*pj[1];
        nvB[2] = (t1B - wwj[2])*oB.z + wwiB*pj[2];
        nvB[3] = (t1B - wwj[3])*oB.w + wwiB*pj[3];
        __stcs((float4*)(Ob + (size_t)ii0*NN),     make_float4(nvA[0],nvA[1],nvA[2],nvA[3]));
        __stcs((float4*)(Ob + (size_t)(ii0+1)*NN), make_float4(nvB[0],nvB[1],nvB[2],nvB[3]));
        // 8 reduction values, butterflies interleaved; packed A/B adds
        float fA[NR], fB[NR];
        #pragma unroll
        for (int r = 0; r < NR; r++){
            fA[r] = nvA[0]*rwj[r][0] + nvA[1]*rwj[r][1] + nvA[2]*rwj[r][2] + nvA[3]*rwj[r][3];
            fB[r] = nvB[0]*rwj[r][0] + nvB[1]*rwj[r][1] + nvB[2]*rwj[r][2] + nvB[3]*rwj[r][3];
        }
        #pragma unroll
        for (int off = 1; off < 32; off <<= 1){
            #pragma unroll
            for (int r = 0; r < NR; r++){
                float tA = __shfl_xor_sync(0xffffffffu, fA[r], off);
                float tB = __shfl_xor_sync(0xffffffffu, fB[r], off);
                add_f32x2(fA[r], fB[r], tA, tB);
            }
        }
        if (lane == 0){
            #pragma unroll
            for (int r = 0; r < NR; r++){
                sfwd[ii0][r][wrp]   = fA[r];
                sfwd[ii0+1][r][wrp] = fB[r];
            }
        }
        #pragma unroll
        for (int r = 0; r < NR; r++){
            float rwiA = rwi_s[r][ii0], rwiB = rwi_s[r][ii0+1];
            #pragma unroll
            for (int k = 0; k < 4; k++) bwd[r][k] += rwiA*nvA[k] + rwiB*nvB[k];
        }
    }
    // diag fix: 32 threads own the block's 128 diagonal elements
    if (jb >= i0 && jb < i0 + TI){
        #pragma unroll
        for (int k = 0; k < 4; k++){
            int ii = jb - i0 + k;               // row; column jb+k == i0+ii
            float wwi = wwi_s[ii];
            float oldd = Lb[(size_t)ii*NN + k];
            float v = (1.f - wwi - wwj[k])*oldd + wwi*pj[k];
            Ob[(size_t)ii*NN + k] = 0.f;
            #pragma unroll
            for (int r = 0; r < NR; r++){
                bwd[r][k] -= rwi_s[r][ii]*v;
                cfix[ii][r] = v*rwj[r][k];
            }
        }
    }
    __syncthreads();
    {   // fwd reduce: 512 outputs (TI*NR), one per thread
        int ii = tid >> 2, r = tid & 3;
        float s = -cfix[ii][r];
        #pragma unroll
        for (int w = 0; w < 16; w++) s += sfwd[ii][r][w];
        g_fwd[(b*NR+r)*NN + i0 + ii] = s;
    }
    #pragma unroll
    for (int r = 0; r < NR; r++)
        #pragma unroll
        for (int k = 0; k < 4; k++) atomicAdd(&g_bwd[(b*NR+r)*NN + jb + k], bwd[r][k]);
}

// ---- rw_new mix + read vectors (partial over 64-n chunks, atomics into out) ----
__global__ void k_rvrw(float* __restrict__ out){
    __shared__ float tile[64*WC];
    __shared__ float srw[NR*64];
    int b = blockIdx.x >> 5;
    int c = blockIdx.x & 31;
    int tid = threadIdx.x;
    int r = tid >> 6, idx = tid & 63;
    int n0 = c*64, n = n0 + idx;
    float m0r = g_rmraw[b*12 + r*3 + 0];
    float m1r = g_rmraw[b*12 + r*3 + 1];
    float m2r = g_rmraw[b*12 + r*3 + 2];
    float mx = fmaxf(m0r, fmaxf(m1r, m2r));
    float e0 = expf(m0r-mx), e1 = expf(m1r-mx), e2 = expf(m2r-mx);
    float inv = 1.f/(e0+e1+e2);
    int base = (b*NR+r)*NN;
    float rwv = e0*inv*g_bwd[base+n] + e1*inv*g_fwd[base+n] + e2*inv*g_rcw[base+n];
    out[OFF_RW + base + n] = rwv;
    srw[r*64 + idx] = rwv;
    for (int i = tid; i < 64*WC; i += 256)
        tile[i] = out[OFF_MEM + ((size_t)b*NN + n0)*WC + i];
    __syncthreads();
    float acc = 0.f;
    #pragma unroll 8
    for (int i = 0; i < 64; i++) acc += srw[r*64 + i]*tile[i*WC + idx];
    atomicAdd(&out[OFF_RV + b*256 + r*64 + idx], acc);
}

extern "C" void kernel_launch(void* const* d_in, const int* in_sizes, int n_in,
                              void* d_out, int out_size){
    const float* x        = (const float*)d_in[0];
    const float* memory   = (const float*)d_in[1];
    const float* link_old = (const float*)d_in[2];
    const float* prec     = (const float*)d_in[3];
    const float* rw_old   = (const float*)d_in[4];
    const float* ww_old   = (const float*)d_in[5];
    const float* usage0   = (const float*)d_in[6];
    CP cp;
    for (int s = 0; s < 10; s++){
        cp.W[s]    = (const float*)d_in[7 + 2*s];
        cp.bvec[s] = (const float*)d_in[8 + 2*s];
    }
    const float* W_fg = cp.W[6];
    const float* b_fg = cp.bvec[6];
    float* out = (float*)d_out;

    static cudaStream_t s1 = nullptr;
    static cudaEvent_t eF = nullptr, eA = nullptr, e1 = nullptr, e2 = nullptr;
    if (!s1){
        cudaStreamCreateWithFlags(&s1, cudaStreamNonBlocking);
        cudaEventCreateWithFlags(&eF, cudaEventDisableTiming);
        cudaEventCreateWithFlags(&eA, cudaEventDisableTiming);
        cudaEventCreateWithFlags(&e1, cudaEventDisableTiming);
        cudaEventCreateWithFlags(&e2, cudaEventDisableTiming);
    }

    // FORK: side stream joins capture via event before any launch on it.
    cudaEventRecord(eF, 0);
    cudaStreamWaitEvent(s1, eF, 0);

    // main: alloc -> [join e1] -> link(inline ww) -> [join e2] -> rvrw
    // side: ctrl -> wcwlog(+zero) -> (e1) -> [wait eA] -> ww -> memnew -> rcwsm -> (e2)
    k_alloc <<<NB, 1024>>>(usage0, ww_old, rw_old, x, W_fg, b_fg, out);  // main
    cudaEventRecord(eA, 0);

    k_ctrl  <<<59, 256, 0, s1>>>(x, cp);                                 // side
    k_wcwlog<<<NB*8, 256, 0, s1>>>(memory, out);                         // side
    cudaEventRecord(e1, s1);
    cudaStreamWaitEvent(s1, eA, 0);

    cudaStreamWaitEvent(0, e1, 0);
    k_link  <<<dim3(NN/TI, NB), 512>>>(link_old, prec, rw_old, out);     // main (big)

    k_ww    <<<NB*8, 256, 0, s1>>>(prec, out);                           // side
    k_memnew<<<NB*256, 256, 0, s1>>>(memory, out);                       // side
    k_rcwsm <<<NB*NR, 256, 0, s1>>>();                                   // side
    cudaEventRecord(e2, s1);
    cudaStreamWaitEvent(0, e2, 0);

    k_rvrw  <<<NB*32, 256>>>(out);                                       // main
}

// round 15
// speedup vs baseline: 1.0446x; 1.0247x over previous
#include <cuda_runtime.h>
#include <math.h>

#define NB 16
#define NN 2048
#define WC 64
#define NR 4
#define NI 512
#define DELTAF 1e-6f
#define TI 128

// ---- output offsets (flattened tuple order) ----
#define OFF_RV    0
#define OFF_MEM   (NB*NR*WC)                 // 4096
#define OFF_LINK  (OFF_MEM + NB*NN*WC)       // 2101248
#define OFF_PREC  (OFF_LINK + NB*NN*NN)      // 69210112
#define OFF_RW    (OFF_PREC + NB*NN)         // 69242880
#define OFF_WW    (OFF_RW + NB*NR*NN)        // 69373952
#define OFF_USAGE (OFF_WW + NB*NN)           // 69406720

// ---- device scratch ----
__device__ float g_readkeys[NB*NR*WC];
__device__ float g_rs[NB*NR];
__device__ float g_wkey[NB*WC];
__device__ float g_wstr[NB];
__device__ float g_ev[NB*WC];
__device__ float g_wv[NB*WC];
__device__ float g_fg[NB*NR];
__device__ float g_ag[NB];
__device__ float g_wg[NB];
__device__ float g_rmraw[NB*12];
__device__ float g_wcwlog[NB*NN];   // exp(logit) values
__device__ float g_wcwsum[NB];      // per-batch sum of exp
__device__ float g_allocsum[NB];    // per-batch sum of alloc
__device__ float g_alloc[NB*NN];
__device__ float g_fwd[NB*NR*NN];   // direct stores
__device__ float g_bwd[NB*NR*NN];   // atomic accumulated
__device__ float g_rcw[NB*NR*NN];   // logits -> softmaxed in place

struct CP { const float* W[10]; const float* bvec[10]; };

// shuffle butterfly (redux.f32 does NOT exist on sm_103 — verified R11)
__device__ __forceinline__ float warp_sum(float v){
    #pragma unroll
    for (int off = 1; off < 32; off <<= 1) v += __shfl_xor_sync(0xffffffffu, v, off);
    return v;
}

// interleaved 4-value warp reduce: input f[0..3] (per-lane partials for 4 r's),
// output: full-warp sum for r = ((lane&1)<<1)|((lane>>1)&1), valid on ALL lanes.
// 18 ops vs 40 for four naive butterflies.
__device__ __forceinline__ float warp_sum4(const float f[4], int lane){
    bool p1 = lane & 1;
    float s0 = p1 ? f[0] : f[2];
    float s1 = p1 ? f[1] : f[3];
    float r0 = __shfl_xor_sync(0xffffffffu, s0, 1);
    float r1 = __shfl_xor_sync(0xffffffffu, s1, 1);
    float g0 = (p1 ? f[2] : f[0]) + r0;
    float g1 = (p1 ? f[3] : f[1]) + r1;
    bool p2 = lane & 2;
    float s2 = p2 ? g0 : g1;
    float r2 = __shfl_xor_sync(0xffffffffu, s2, 2);
    float v  = (p2 ? g1 : g0) + r2;
    v += __shfl_xor_sync(0xffffffffu, v, 4);
    v += __shfl_xor_sync(0xffffffffu, v, 8);
    v += __shfl_xor_sync(0xffffffffu, v, 16);
    return v;
}

__device__ __forceinline__ float act_apply(int code, float v){
    switch(code){
        case 0: return tanhf(v);
        case 1: return fmaxf(v, 0.f) + log1pf(expf(-fabsf(v)));  // softplus
        case 2: return 1.f/(1.f + expf(-v));                      // sigmoid
        default: return v;
    }
}

__device__ __forceinline__ float* seg_out(int seg){
    switch(seg){
        case 0: return g_readkeys;
        case 1: return g_rs;
        case 2: return g_wkey;
        case 3: return g_wstr;
        case 4: return g_ev;
        case 5: return g_wv;
        case 6: return g_fg;
        case 7: return g_ag;
        case 8: return g_wg;
        default: return g_rmraw;
    }
}

// ---- controller projections: one warp per output row (471 rows) ----
__global__ void k_ctrl(const float* __restrict__ x, CP cp){
    __shared__ float sx[NB*NI];
    int tid = threadIdx.x;
    if (blockIdx.x == 0 && tid < NB) g_wcwsum[tid] = 0.f;   // zero before wcwlog atomics
    for (int i = tid; i < NB*NI; i += blockDim.x) sx[i] = x[i];
    __syncthreads();
    int gw = (blockIdx.x*blockDim.x + tid) >> 5;
    int lane = tid & 31;
    if (gw >= 471) return;
    const int segStart[10] = {0,256,260,324,325,389,453,457,458,459};
    const int segLen[10]   = {256,4,64,1,64,64,4,1,1,12};
    const int segAct[10]   = {0,1,0,1,2,0,2,2,2,3};
    int seg = 0;
    for (int s = 9; s >= 0; s--){ if (gw >= segStart[s]){ seg = s; break; } }
    int rl = gw - segStart[seg];
    const float* W = cp.W[seg] + rl*NI;
    float wreg[16];
    #pragma unroll
    for (int s = 0; s < 16; s++) wreg[s] = W[s*32 + lane];
    float bias = cp.bvec[seg][rl];
    float* outp = seg_out(seg);
    int sl = segLen[seg], ac = segAct[seg];
    for (int b = 0; b < NB; b++){
        const float* xb = &sx[b*NI];
        float sum = 0.f;
        #pragma unroll
        for (int s = 0; s < 16; s++) sum += wreg[s]*xb[s*32 + lane];
        sum = warp_sum(sum);
        if (lane == 0) outp[b*sl + rl] = act_apply(ac, sum + bias);
    }
}

// ---- write-content exp(logits) + per-batch sum (+ folded zeroing) ----
__global__ void k_wcwlog(const float* __restrict__ mem, float* __restrict__ out){
    __shared__ float skey[WC];
    __shared__ float rbuf[8];
    int b = blockIdx.x >> 3;
    int c = blockIdx.x & 7;
    int tid = threadIdx.x;
    int lane = tid & 31, wid = tid >> 5;
    // folded zero: 32768 threads cover bwd (131072) + RV (4096)
    {
        int gt = blockIdx.x*256 + tid;
        #pragma unroll
        for (int k = 0; k < 4; k++) g_bwd[k*32768 + gt] = 0.f;
        if (gt < NB*NR*WC) out[OFF_RV + gt] = 0.f;
    }
    if (tid < WC) skey[tid] = g_wkey[b*WC + tid];
    __syncthreads();
    float kn2 = 0.f;
    #pragma unroll
    for (int i = 0; i < WC; i++) kn2 += skey[i]*skey[i];
    float kn = sqrtf(kn2);
    float beta = g_wstr[b];
    int n = c*256 + tid;
    const float4* row = (const float4*)(mem + ((size_t)b*NN + n)*WC);
    float dot = 0.f, sq = 0.f;
    #pragma unroll
    for (int i = 0; i < WC/4; i++){
        float4 m = row[i];
        dot += m.x*skey[4*i] + m.y*skey[4*i+1] + m.z*skey[4*i+2] + m.w*skey[4*i+3];
        sq  += m.x*m.x + m.y*m.y + m.z*m.z + m.w*m.w;
    }
    float e = expf(beta*dot/(kn*sqrtf(sq) + DELTAF));
    g_wcwlog[b*NN + n] = e;
    float s = warp_sum(e);
    if (lane == 0) rbuf[wid] = s;
    __syncthreads();
    if (tid == 0){
        float t = 0.f;
        #pragma unroll
        for (int w = 0; w < 8; w++) t += rbuf[w];
        atomicAdd(&g_wcwsum[b], t);
    }
}

// ---- usage + allocation (free gates inline) + allocsum ----
__global__ void __launch_bounds__(1024)
k_alloc(const float* __restrict__ u0v, const float* __restrict__ wwold,
        const float* __restrict__ rwold, const float* __restrict__ x,
        const float* __restrict__ W_fg, const float* __restrict__ b_fg,
        float* __restrict__ out){
    __shared__ unsigned keys[NN];
    __shared__ float su[NN];
    __shared__ float warptot[32];
    __shared__ float warpoff[32];
    __shared__ float sfg[NR];
    int b = blockIdx.x, tid = threadIdx.x;   // 1024 threads
    int lane = tid & 31, wid = tid >> 5;
    if (wid < NR){
        int r = wid;
        float s = 0.f;
        #pragma unroll
        for (int i = 0; i < 16; i++)
            s += x[b*NI + i*32 + lane]*W_fg[r*NI + i*32 + lane];
        s = warp_sum(s);
        if (lane == 0) sfg[r] = 1.f/(1.f + expf(-(s + b_fg[r])));
    }
    __syncthreads();
    for (int i = tid; i < NN; i += 1024){
        float u0 = u0v[b*NN + i];
        float u = u0 + (1.f - u0)*wwold[b*NN + i];
        float ret = 1.f;
        #pragma unroll
        for (int r = 0; r < NR; r++) ret *= (1.f - sfg[r]*rwold[(b*NR+r)*NN + i]);
        float usage = u*ret;
        out[OFF_USAGE + b*NN + i] = usage;
        float uu = DELTAF + (1.f - DELTAF)*usage;
        su[i] = uu;
        keys[i] = (__float_as_uint(uu) & 0xFFFFF800u) | (unsigned)i;
    }
    __syncthreads();
    for (int k = 2; k <= NN; k <<= 1){
        for (int j = k >> 1; j > 0; j >>= 1){
            #pragma unroll
            for (int h = 0; h < 2; h++){
                int i = h*1024 + tid;
                int ixj = i ^ j;
                if (ixj > i){
                    bool up = ((i & k) == 0);
                    unsigned a = keys[i], c = keys[ixj];
                    if (up ? (a > c) : (a < c)){ keys[i] = c; keys[ixj] = a; }
                }
            }
            if (j >= 32) __syncthreads(); else __syncwarp();
        }
        if (k >= 32) __syncthreads();
    }
    __syncthreads();
    unsigned k0 = keys[2*tid], k1 = keys[2*tid + 1];
    float u0s = su[k0 & 0x7FFu];
    float u1s = su[k1 & 0x7FFu];
    float incl = u0s*u1s;
    #pragma unroll
    for (int d = 1; d < 32; d <<= 1){
        float v = __shfl_up_sync(0xffffffffu, incl, d);
        if (lane >= d) incl *= v;
    }
    if (lane == 31) warptot[wid] = incl;
    __syncthreads();
    if (wid == 0){
        float winc = warptot[lane];
        #pragma unroll
        for (int d = 1; d < 32; d <<= 1){
            float v = __shfl_up_sync(0xffffffffu, winc, d);
            if (lane >= d) winc *= v;
        }
        float wex = __shfl_up_sync(0xffffffffu, winc, 1);
        if (lane == 0) wex = 1.f;
        warpoff[lane] = wex;
    }
    __syncthreads();
    float excl = __shfl_up_sync(0xffffffffu, incl, 1);
    if (lane == 0) excl = 1.f;
    float pre0 = warpoff[wid]*excl;
    float pre1 = pre0*u0s;
    float a0 = (1.f - u0s)*pre0;
    float a1 = (1.f - u1s)*pre1;
    g_alloc[b*NN + (k0 & 0x7FFu)] = a0;
    g_alloc[b*NN + (k1 & 0x7FFu)] = a1;
    float asum = warp_sum(a0 + a1);
    __syncthreads();
    if (lane == 0) warptot[wid] = asum;
    __syncthreads();
    if (tid == 0){
        float t = 0.f;
        #pragma unroll
        for (int w = 0; w < 32; w++) t += warptot[w];
        g_allocsum[b] = t;
    }
}

// ---- ww + precedence outputs (side stream; not on critical path) ----
__global__ void k_ww(const float* __restrict__ prec_old, float* __restrict__ out){
    int b = blockIdx.x >> 3;
    int n = (blockIdx.x & 7)*256 + threadIdx.x;
    float inv = 1.f/g_wcwsum[b];
    float agv = g_ag[b], wgv = g_wg[b];
    float S = wgv*(agv*g_allocsum[b] + (1.f - agv));
    float w = wgv*(agv*g_alloc[b*NN+n] + (1.f-agv)*g_wcwlog[b*NN+n]*inv);
    out[OFF_WW + b*NN + n] = w;
    out[OFF_PREC + b*NN + n] = (1.f - S)*prec_old[b*NN + n] + w;
}

// ---- memory update + read-content logits (fused), one warp per row ----
__global__ void k_memnew(const float* __restrict__ mem, float* __restrict__ out){
    __shared__ float skey[NR*WC];
    __shared__ float sknorm[NR];
    __shared__ float sev[WC], swv[WC];
    int b = blockIdx.x >> 8;
    int rowblk = blockIdx.x & 255;
    int tid = threadIdx.x;
    skey[tid] = g_readkeys[b*NR*WC + tid];
    if (tid < WC){ sev[tid] = g_ev[b*WC + tid]; swv[tid] = g_wv[b*WC + tid]; }
    __syncthreads();
    if (tid < NR){
        float s = 0.f;
        #pragma unroll
        for (int i = 0; i < WC; i++){ float v = skey[tid*WC + i]; s += v*v; }
        sknorm[tid] = sqrtf(s);
    }
    __syncthreads();
    int wrp = tid >> 5, lane = tid & 31;
    int n = rowblk*8 + wrp;
    int row = b*NN + n;
    int w0 = lane*2;
    float2 m = *(const float2*)(mem + (size_t)row*WC + w0);
    float ww = out[OFF_WW + row];
    float n0 = m.x*(1.f - ww*sev[w0])   + ww*swv[w0];
    float n1 = m.y*(1.f - ww*sev[w0+1]) + ww*swv[w0+1];
    *(float2*)(out + OFF_MEM + (size_t)row*WC + w0) = make_float2(n0, n1);
    float d[NR], sq = warp_sum(n0*n0 + n1*n1);
    #pragma unroll
    for (int r = 0; r < NR; r++)
        d[r] = warp_sum(n0*skey[r*WC + w0] + n1*skey[r*WC + w0 + 1]);
    if (lane == 0){
        float mn = sqrtf(sq);
        #pragma unroll
        for (int r = 0; r < NR; r++)
            g_rcw[(b*NR+r)*NN + n] = g_rs[b*NR+r]*d[r]/(sknorm[r]*mn + DELTAF);
    }
}

// ---- read-content softmax (in place), one block per (b,r) ----
__global__ void k_rcwsm(){
    __shared__ float sl[NN];
    __shared__ float rbuf[256];
    int base = blockIdx.x*NN;
    int tid = threadIdx.x;
    float mx = -1e30f;
    #pragma unroll
    for (int k = 0; k < 8; k++){
        float v = g_rcw[base + k*256 + tid];
        sl[k*256 + tid] = v;
        mx = fmaxf(mx, v);
    }
    rbuf[tid] = mx; __syncthreads();
    for (int s = 128; s; s >>= 1){ if (tid < s) rbuf[tid] = fmaxf(rbuf[tid], rbuf[tid+s]); __syncthreads(); }
    mx = rbuf[0]; __syncthreads();
    float sum = 0.f;
    #pragma unroll
    for (int k = 0; k < 8; k++){
        float e = expf(sl[k*256 + tid] - mx);
        sl[k*256 + tid] = e; sum += e;
    }
    rbuf[tid] = sum; __syncthreads();
    for (int s = 128; s; s >>= 1){ if (tid < s) rbuf[tid] += rbuf[tid+s]; __syncthreads(); }
    float inv = 1.f/rbuf[0];
    #pragma unroll
    for (int k = 0; k < 8; k++) g_rcw[base + k*256 + tid] = sl[k*256 + tid]*inv;
}

// ---- fused link update + fwd/bwd: 512 threads, 4 j-cols/thread,
//      2-row batching + interleaved 4-value warp reduction ----
__global__ void __launch_bounds__(512, 2)
k_link(const float* __restrict__ link_old, const float* __restrict__ prec_old,
       const float* __restrict__ rw_old, float* __restrict__ out){
    __shared__ float wwi_s[TI];
    __shared__ float rwi_s[NR][TI];
    __shared__ float sfwd[TI][NR][17];   // 16 warp-partials + pad
    __shared__ float cfix[TI][NR];       // diag corrections for fwd
    int b = blockIdx.y;
    int i0 = blockIdx.x * TI;
    int tid = threadIdx.x;
    int wrp = tid >> 5, lane = tid & 31;
    float inv = 1.f/g_wcwsum[b];
    float agv = g_ag[b], wgv = g_wg[b];
    float c_alloc = wgv*agv;
    float c_cw = wgv*(1.f-agv)*inv;
    if (tid < TI)
        wwi_s[tid] = c_alloc*g_alloc[b*NN + i0 + tid] + c_cw*g_wcwlog[b*NN + i0 + tid];
    {   // 512 threads load 512 rwi values
        int r = tid >> 7, ii = tid & 127;
        rwi_s[r][ii] = rw_old[(b*NR+r)*NN + i0 + ii];
    }
    int jb = tid * 4;
    float wwj[4], pj[4], rwj[NR][4];
    #pragma unroll
    for (int k = 0; k < 4; k++){
        wwj[k] = c_alloc*g_alloc[b*NN + jb + k] + c_cw*g_wcwlog[b*NN + jb + k];
        pj[k]  = prec_old[b*NN + jb + k];
    }
    #pragma unroll
    for (int r = 0; r < NR; r++)
        #pragma unroll
        for (int k = 0; k < 4; k++) rwj[r][k] = rw_old[(b*NR+r)*NN + jb + k];
    float bwd[NR][4];
    #pragma unroll
    for (int r = 0; r < NR; r++)
        #pragma unroll
        for (int k = 0; k < 4; k++) bwd[r][k] = 0.f;
    __syncthreads();
    const float* Lb = link_old + ((size_t)b*NN + i0)*NN + jb;
    float* Ob = out + OFF_LINK + ((size_t)b*NN + i0)*NN + jb;
    int rsel = ((lane & 1) << 1) | ((lane >> 1) & 1);   // r owned by this lane after warp_sum4
    #pragma unroll 2
    for (int ii0 = 0; ii0 < TI; ii0 += 2){
        // both rows' loads issued up front (MLP x2; ptxas batches across unroll)
        float4 oA = __ldcs((const float4*)(Lb + (size_t)ii0*NN));
        float4 oB = __ldcs((const float4*)(Lb + (size_t)(ii0+1)*NN));
        float wwiA = wwi_s[ii0],   t1A = 1.f - wwiA;
        float wwiB = wwi_s[ii0+1], t1B = 1.f - wwiB;
        float nvA[4], nvB[4];
        nvA[0] = (t1A - wwj[0])*oA.x + wwiA*pj[0];
        nvA[1] = (t1A - wwj[1])*oA.y + wwiA*pj[1];
        nvA[2] = (t1A - wwj[2])*oA.z + wwiA*pj[2];
        nvA[3] = (t1A - wwj[3])*oA.w + wwiA*pj[3];
        nvB[0] = (t1B - wwj[0])*oB.x + wwiB*pj[0];
        nvB[1] = (t1B - wwj[1])*oB.y + wwiB*pj[1];
        nvB[2] = (t1B - wwj[2])*oB.z + wwiB*pj[2];
        nvB[3] = (t1B - wwj[3])*oB.w + wwiB*pj[3];
        __stcs((float4*)(Ob + (size_t)ii0*NN),     make_float4(nvA[0],nvA[1],nvA[2],nvA[3]));
        __stcs((float4*)(Ob + (size_t)(ii0+1)*NN), make_float4(nvB[0],nvB[1],nvB[2],nvB[3]));
        float fA[NR], fB[NR];
        #pragma unroll
        for (int r = 0; r < NR; r++){
            fA[r] = nvA[0]*rwj[r][0] + nvA[1]*rwj[r][1] + nvA[2]*rwj[r][2] + nvA[3]*rwj[r][3];
            fB[r] = nvB[0]*rwj[r][0] + nvB[1]*rwj[r][1] + nvB[2]*rwj[r][2] + nvB[3]*rwj[r][3];
        }
        float vA = warp_sum4(fA, lane);
        float vB = warp_sum4(fB, lane);
        if (lane < 4){
            sfwd[ii0][rsel][wrp]   = vA;
            sfwd[ii0+1][rsel][wrp] = vB;
        }
        #pragma unroll
        for (int r = 0; r < NR; r++){
            float rwiA = rwi_s[r][ii0], rwiB = rwi_s[r][ii0+1];
            #pragma unroll
            for (int k = 0; k < 4; k++) bwd[r][k] += rwiA*nvA[k] + rwiB*nvB[k];
        }
    }
    // diag fix: 32 threads own the block's 128 diagonal elements
    if (jb >= i0 && jb < i0 + TI){
        #pragma unroll
        for (int k = 0; k < 4; k++){
            int ii = jb - i0 + k;               // row; column jb+k == i0+ii
            float wwi = wwi_s[ii];
            float oldd = Lb[(size_t)ii*NN + k];
            float v = (1.f - wwi - wwj[k])*oldd + wwi*pj[k];
            Ob[(size_t)ii*NN + k] = 0.f;
            #pragma unroll
            for (int r = 0; r < NR; r++){
                bwd[r][k] -= rwi_s[r][ii]*v;
                cfix[ii][r] = v*rwj[r][k];
            }
        }
    }
    __syncthreads();
    {   // fwd reduce: 512 outputs (TI*NR), one per thread
        int ii = tid >> 2, r = tid & 3;
        float s = -cfix[ii][r];
        #pragma unroll
        for (int w = 0; w < 16; w++) s += sfwd[ii][r][w];
        g_fwd[(b*NR+r)*NN + i0 + ii] = s;
    }
    #pragma unroll
    for (int r = 0; r < NR; r++)
        #pragma unroll
        for (int k = 0; k < 4; k++) atomicAdd(&g_bwd[(b*NR+r)*NN + jb + k], bwd[r][k]);
}

// ---- rw_new mix + read vectors (partial over 64-n chunks, atomics into out) ----
__global__ void k_rvrw(float* __restrict__ out){
    __shared__ float tile[64*WC];
    __shared__ float srw[NR*64];
    int b = blockIdx.x >> 5;
    int c = blockIdx.x & 31;
    int tid = threadIdx.x;
    int r = tid >> 6, idx = tid & 63;
    int n0 = c*64, n = n0 + idx;
    float m0r = g_rmraw[b*12 + r*3 + 0];
    float m1r = g_rmraw[b*12 + r*3 + 1];
    float m2r = g_rmraw[b*12 + r*3 + 2];
    float mx = fmaxf(m0r, fmaxf(m1r, m2r));
    float e0 = expf(m0r-mx), e1 = expf(m1r-mx), e2 = expf(m2r-mx);
    float inv = 1.f/(e0+e1+e2);
    int base = (b*NR+r)*NN;
    float rwv = e0*inv*g_bwd[base+n] + e1*inv*g_fwd[base+n] + e2*inv*g_rcw[base+n];
    out[OFF_RW + base + n] = rwv;
    srw[r*64 + idx] = rwv;
    for (int i = tid; i < 64*WC; i += 256)
        tile[i] = out[OFF_MEM + ((size_t)b*NN + n0)*WC + i];
    __syncthreads();
    float acc = 0.f;
    #pragma unroll 8
    for (int i = 0; i < 64; i++) acc += srw[r*64 + i]*tile[i*WC + idx];
    atomicAdd(&out[OFF_RV + b*256 + r*64 + idx], acc);
}

extern "C" void kernel_launch(void* const* d_in, const int* in_sizes, int n_in,
                              void* d_out, int out_size){
    const float* x        = (const float*)d_in[0];
    const float* memory   = (const float*)d_in[1];
    const float* link_old = (const float*)d_in[2];
    const float* prec     = (const float*)d_in[3];
    const float* rw_old   = (const float*)d_in[4];
    const float* ww_old   = (const float*)d_in[5];
    const float* usage0   = (const float*)d_in[6];
    CP cp;
    for (int s = 0; s < 10; s++){
        cp.W[s]    = (const float*)d_in[7 + 2*s];
        cp.bvec[s] = (const float*)d_in[8 + 2*s];
    }
    const float* W_fg = cp.W[6];
    const float* b_fg = cp.bvec[6];
    float* out = (float*)d_out;

    static cudaStream_t s1 = nullptr;
    static cudaEvent_t eF = nullptr, eA = nullptr, e1 = nullptr, e2 = nullptr;
    if (!s1){
        cudaStreamCreateWithFlags(&s1, cudaStreamNonBlocking);
        cudaEventCreateWithFlags(&eF, cudaEventDisableTiming);
        cudaEventCreateWithFlags(&eA, cudaEventDisableTiming);
        cudaEventCreateWithFlags(&e1, cudaEventDisableTiming);
        cudaEventCreateWithFlags(&e2, cudaEventDisableTiming);
    }

    // FORK: side stream joins capture via event before any launch on it.
    cudaEventRecord(eF, 0);
    cudaStreamWaitEvent(s1, eF, 0);

    // main: alloc -> [join e1] -> link(inline ww) -> [join e2] -> rvrw
    // side: ctrl -> wcwlog(+zero) -> (e1) -> [wait eA] -> ww -> memnew -> rcwsm -> (e2)
    k_alloc <<<NB, 1024>>>(usage0, ww_old, rw_old, x, W_fg, b_fg, out);  // main
    cudaEventRecord(eA, 0);

    k_ctrl  <<<59, 256, 0, s1>>>(x, cp);                                 // side
    k_wcwlog<<<NB*8, 256, 0, s1>>>(memory, out);                         // side
    cudaEventRecord(e1, s1);
    cudaStreamWaitEvent(s1, eA, 0);

    cudaStreamWaitEvent(0, e1, 0);
    k_link  <<<dim3(NN/TI, NB), 512>>>(link_old, prec, rw_old, out);     // main (big)

    k_ww    <<<NB*8, 256, 0, s1>>>(prec, out);                           // side
    k_memnew<<<NB*256, 256, 0, s1>>>(memory, out);                       // side
    k_rcwsm <<<NB*NR, 256, 0, s1>>>();                                   // side
    cudaEventRecord(e2, s1);
    cudaStreamWaitEvent(0, e2, 0);

    k_rvrw  <<<NB*32, 256>>>(out);                                       // main
}

// round 16
// speedup vs baseline: 1.0541x; 1.0091x over previous
#include <cuda_runtime.h>
#include <math.h>

#define NB 16
#define NN 2048
#define WC 64
#define NR 4
#define NI 512
#define DELTAF 1e-6f
#define TI 128

// ---- output offsets (flattened tuple order) ----
#define OFF_RV    0
#define OFF_MEM   (NB*NR*WC)                 // 4096
#define OFF_LINK  (OFF_MEM + NB*NN*WC)       // 2101248
#define OFF_PREC  (OFF_LINK + NB*NN*NN)      // 69210112
#define OFF_RW    (OFF_PREC + NB*NN)         // 69242880
#define OFF_WW    (OFF_RW + NB*NR*NN)        // 69373952
#define OFF_USAGE (OFF_WW + NB*NN)           // 69406720

// ---- device scratch ----
__device__ float g_readkeys[NB*NR*WC];
__device__ float g_rs[NB*NR];
__device__ float g_wkey[NB*WC];
__device__ float g_wstr[NB];
__device__ float g_ev[NB*WC];
__device__ float g_wv[NB*WC];
__device__ float g_fg[NB*NR];
__device__ float g_ag[NB];
__device__ float g_wg[NB];
__device__ float g_rmraw[NB*12];
__device__ float g_wcwlog[NB*NN];   // exp(logit) values
__device__ float g_wcwsum[NB];      // per-batch sum of exp
__device__ float g_allocsum[NB];    // per-batch sum of alloc
__device__ float g_alloc[NB*NN];
__device__ float g_fwd[NB*NR*NN];   // direct stores
__device__ float g_bwd[NB*NR*NN];   // atomic accumulated
__device__ float g_rcw[NB*NR*NN];   // logits -> softmaxed in place

struct CP { const float* W[10]; const float* bvec[10]; };

// shuffle butterfly (redux.f32 does NOT exist on sm_103 — verified R11)
__device__ __forceinline__ float warp_sum(float v){
    #pragma unroll
    for (int off = 1; off < 32; off <<= 1) v += __shfl_xor_sync(0xffffffffu, v, off);
    return v;
}

// interleaved 4-value warp reduce: input f[0..3] (per-lane partials for 4 r's),
// output: full-warp sum for r = ((lane&1)<<1)|((lane>>1)&1), valid on ALL lanes.
__device__ __forceinline__ float warp_sum4(const float f[4], int lane){
    bool p1 = lane & 1;
    float s0 = p1 ? f[0] : f[2];
    float s1 = p1 ? f[1] : f[3];
    float r0 = __shfl_xor_sync(0xffffffffu, s0, 1);
    float r1 = __shfl_xor_sync(0xffffffffu, s1, 1);
    float g0 = (p1 ? f[2] : f[0]) + r0;
    float g1 = (p1 ? f[3] : f[1]) + r1;
    bool p2 = lane & 2;
    float s2 = p2 ? g0 : g1;
    float r2 = __shfl_xor_sync(0xffffffffu, s2, 2);
    float v  = (p2 ? g1 : g0) + r2;
    v += __shfl_xor_sync(0xffffffffu, v, 4);
    v += __shfl_xor_sync(0xffffffffu, v, 8);
    v += __shfl_xor_sync(0xffffffffu, v, 16);
    return v;
}

__device__ __forceinline__ float act_apply(int code, float v){
    switch(code){
        case 0: return tanhf(v);
        case 1: return fmaxf(v, 0.f) + log1pf(expf(-fabsf(v)));  // softplus
        case 2: return 1.f/(1.f + expf(-v));                      // sigmoid
        default: return v;
    }
}

__device__ __forceinline__ float* seg_out(int seg){
    switch(seg){
        case 0: return g_readkeys;
        case 1: return g_rs;
        case 2: return g_wkey;
        case 3: return g_wstr;
        case 4: return g_ev;
        case 5: return g_wv;
        case 6: return g_fg;
        case 7: return g_ag;
        case 8: return g_wg;
        default: return g_rmraw;
    }
}

// ---- controller projections: one warp per output row (471 rows) ----
__global__ void k_ctrl(const float* __restrict__ x, CP cp){
    __shared__ float sx[NB*NI];
    int tid = threadIdx.x;
    if (blockIdx.x == 0 && tid < NB) g_wcwsum[tid] = 0.f;   // zero before wcwlog atomics
    for (int i = tid; i < NB*NI; i += blockDim.x) sx[i] = x[i];
    __syncthreads();
    int gw = (blockIdx.x*blockDim.x + tid) >> 5;
    int lane = tid & 31;
    if (gw >= 471) return;
    const int segStart[10] = {0,256,260,324,325,389,453,457,458,459};
    const int segLen[10]   = {256,4,64,1,64,64,4,1,1,12};
    const int segAct[10]   = {0,1,0,1,2,0,2,2,2,3};
    int seg = 0;
    for (int s = 9; s >= 0; s--){ if (gw >= segStart[s]){ seg = s; break; } }
    int rl = gw - segStart[seg];
    const float* W = cp.W[seg] + rl*NI;
    float wreg[16];
    #pragma unroll
    for (int s = 0; s < 16; s++) wreg[s] = W[s*32 + lane];
    float bias = cp.bvec[seg][rl];
    float* outp = seg_out(seg);
    int sl = segLen[seg], ac = segAct[seg];
    for (int b = 0; b < NB; b++){
        const float* xb = &sx[b*NI];
        float sum = 0.f;
        #pragma unroll
        for (int s = 0; s < 16; s++) sum += wreg[s]*xb[s*32 + lane];
        sum = warp_sum(sum);
        if (lane == 0) outp[b*sl + rl] = act_apply(ac, sum + bias);
    }
}

// ---- write-content exp(logits) + per-batch sum (+ folded zeroing) ----
__global__ void k_wcwlog(const float* __restrict__ mem, float* __restrict__ out){
    __shared__ float skey[WC];
    __shared__ float rbuf[8];
    int b = blockIdx.x >> 3;
    int c = blockIdx.x & 7;
    int tid = threadIdx.x;
    int lane = tid & 31, wid = tid >> 5;
    // folded zero: 32768 threads cover bwd (131072) + RV (4096)
    {
        int gt = blockIdx.x*256 + tid;
        #pragma unroll
        for (int k = 0; k < 4; k++) g_bwd[k*32768 + gt] = 0.f;
        if (gt < NB*NR*WC) out[OFF_RV + gt] = 0.f;
    }
    if (tid < WC) skey[tid] = g_wkey[b*WC + tid];
    __syncthreads();
    float kn2 = 0.f;
    #pragma unroll
    for (int i = 0; i < WC; i++) kn2 += skey[i]*skey[i];
    float kn = sqrtf(kn2);
    float beta = g_wstr[b];
    int n = c*256 + tid;
    const float4* row = (const float4*)(mem + ((size_t)b*NN + n)*WC);
    float dot = 0.f, sq = 0.f;
    #pragma unroll
    for (int i = 0; i < WC/4; i++){
        float4 m = row[i];
        dot += m.x*skey[4*i] + m.y*skey[4*i+1] + m.z*skey[4*i+2] + m.w*skey[4*i+3];
        sq  += m.x*m.x + m.y*m.y + m.z*m.z + m.w*m.w;
    }
    float e = expf(beta*dot/(kn*sqrtf(sq) + DELTAF));
    g_wcwlog[b*NN + n] = e;
    float s = warp_sum(e);
    if (lane == 0) rbuf[wid] = s;
    __syncthreads();
    if (tid == 0){
        float t = 0.f;
        #pragma unroll
        for (int w = 0; w < 8; w++) t += rbuf[w];
        atomicAdd(&g_wcwsum[b], t);
    }
}

// ---- usage + allocation (free gates inline) + allocsum ----
__global__ void __launch_bounds__(1024)
k_alloc(const float* __restrict__ u0v, const float* __restrict__ wwold,
        const float* __restrict__ rwold, const float* __restrict__ x,
        const float* __restrict__ W_fg, const float* __restrict__ b_fg,
        float* __restrict__ out){
    __shared__ unsigned keys[NN];
    __shared__ float su[NN];
    __shared__ float warptot[32];
    __shared__ float warpoff[32];
    __shared__ float sfg[NR];
    int b = blockIdx.x, tid = threadIdx.x;   // 1024 threads
    int lane = tid & 31, wid = tid >> 5;
    if (wid < NR){
        int r = wid;
        float s = 0.f;
        #pragma unroll
        for (int i = 0; i < 16; i++)
            s += x[b*NI + i*32 + lane]*W_fg[r*NI + i*32 + lane];
        s = warp_sum(s);
        if (lane == 0) sfg[r] = 1.f/(1.f + expf(-(s + b_fg[r])));
    }
    __syncthreads();
    for (int i = tid; i < NN; i += 1024){
        float u0 = u0v[b*NN + i];
        float u = u0 + (1.f - u0)*wwold[b*NN + i];
        float ret = 1.f;
        #pragma unroll
        for (int r = 0; r < NR; r++) ret *= (1.f - sfg[r]*rwold[(b*NR+r)*NN + i]);
        float usage = u*ret;
        out[OFF_USAGE + b*NN + i] = usage;
        float uu = DELTAF + (1.f - DELTAF)*usage;
        su[i] = uu;
        keys[i] = (__float_as_uint(uu) & 0xFFFFF800u) | (unsigned)i;
    }
    __syncthreads();
    for (int k = 2; k <= NN; k <<= 1){
        for (int j = k >> 1; j > 0; j >>= 1){
            #pragma unroll
            for (int h = 0; h < 2; h++){
                int i = h*1024 + tid;
                int ixj = i ^ j;
                if (ixj > i){
                    bool up = ((i & k) == 0);
                    unsigned a = keys[i], c = keys[ixj];
                    if (up ? (a > c) : (a < c)){ keys[i] = c; keys[ixj] = a; }
                }
            }
            if (j >= 32) __syncthreads(); else __syncwarp();
        }
        if (k >= 32) __syncthreads();
    }
    __syncthreads();
    unsigned k0 = keys[2*tid], k1 = keys[2*tid + 1];
    float u0s = su[k0 & 0x7FFu];
    float u1s = su[k1 & 0x7FFu];
    float incl = u0s*u1s;
    #pragma unroll
    for (int d = 1; d < 32; d <<= 1){
        float v = __shfl_up_sync(0xffffffffu, incl, d);
        if (lane >= d) incl *= v;
    }
    if (lane == 31) warptot[wid] = incl;
    __syncthreads();
    if (wid == 0){
        float winc = warptot[lane];
        #pragma unroll
        for (int d = 1; d < 32; d <<= 1){
            float v = __shfl_up_sync(0xffffffffu, winc, d);
            if (lane >= d) winc *= v;
        }
        float wex = __shfl_up_sync(0xffffffffu, winc, 1);
        if (lane == 0) wex = 1.f;
        warpoff[lane] = wex;
    }
    __syncthreads();
    float excl = __shfl_up_sync(0xffffffffu, incl, 1);
    if (lane == 0) excl = 1.f;
    float pre0 = warpoff[wid]*excl;
    float pre1 = pre0*u0s;
    float a0 = (1.f - u0s)*pre0;
    float a1 = (1.f - u1s)*pre1;
    g_alloc[b*NN + (k0 & 0x7FFu)] = a0;
    g_alloc[b*NN + (k1 & 0x7FFu)] = a1;
    float asum = warp_sum(a0 + a1);
    __syncthreads();
    if (lane == 0) warptot[wid] = asum;
    __syncthreads();
    if (tid == 0){
        float t = 0.f;
        #pragma unroll
        for (int w = 0; w < 32; w++) t += warptot[w];
        g_allocsum[b] = t;
    }
}

// ---- ww + precedence outputs (side stream; not on critical path) ----
__global__ void k_ww(const float* __restrict__ prec_old, float* __restrict__ out){
    int b = blockIdx.x >> 3;
    int n = (blockIdx.x & 7)*256 + threadIdx.x;
    float inv = 1.f/g_wcwsum[b];
    float agv = g_ag[b], wgv = g_wg[b];
    float S = wgv*(agv*g_allocsum[b] + (1.f - agv));
    float w = wgv*(agv*g_alloc[b*NN+n] + (1.f-agv)*g_wcwlog[b*NN+n]*inv);
    out[OFF_WW + b*NN + n] = w;
    out[OFF_PREC + b*NN + n] = (1.f - S)*prec_old[b*NN + n] + w;
}

// ---- memory update + read-content logits (fused), one warp per row ----
__global__ void k_memnew(const float* __restrict__ mem, float* __restrict__ out){
    __shared__ float skey[NR*WC];
    __shared__ float sknorm[NR];
    __shared__ float sev[WC], swv[WC];
    int b = blockIdx.x >> 8;
    int rowblk = blockIdx.x & 255;
    int tid = threadIdx.x;
    skey[tid] = g_readkeys[b*NR*WC + tid];
    if (tid < WC){ sev[tid] = g_ev[b*WC + tid]; swv[tid] = g_wv[b*WC + tid]; }
    __syncthreads();
    if (tid < NR){
        float s = 0.f;
        #pragma unroll
        for (int i = 0; i < WC; i++){ float v = skey[tid*WC + i]; s += v*v; }
        sknorm[tid] = sqrtf(s);
    }
    __syncthreads();
    int wrp = tid >> 5, lane = tid & 31;
    int n = rowblk*8 + wrp;
    int row = b*NN + n;
    int w0 = lane*2;
    float2 m = *(const float2*)(mem + (size_t)row*WC + w0);
    float ww = out[OFF_WW + row];
    float n0 = m.x*(1.f - ww*sev[w0])   + ww*swv[w0];
    float n1 = m.y*(1.f - ww*sev[w0+1]) + ww*swv[w0+1];
    *(float2*)(out + OFF_MEM + (size_t)row*WC + w0) = make_float2(n0, n1);
    float d[NR], sq = warp_sum(n0*n0 + n1*n1);
    #pragma unroll
    for (int r = 0; r < NR; r++)
        d[r] = warp_sum(n0*skey[r*WC + w0] + n1*skey[r*WC + w0 + 1]);
    if (lane == 0){
        float mn = sqrtf(sq);
        #pragma unroll
        for (int r = 0; r < NR; r++)
            g_rcw[(b*NR+r)*NN + n] = g_rs[b*NR+r]*d[r]/(sknorm[r]*mn + DELTAF);
    }
}

// ---- read-content softmax (in place), one block per (b,r) ----
__global__ void k_rcwsm(){
    __shared__ float sl[NN];
    __shared__ float rbuf[256];
    int base = blockIdx.x*NN;
    int tid = threadIdx.x;
    float mx = -1e30f;
    #pragma unroll
    for (int k = 0; k < 8; k++){
        float v = g_rcw[base + k*256 + tid];
        sl[k*256 + tid] = v;
        mx = fmaxf(mx, v);
    }
    rbuf[tid] = mx; __syncthreads();
    for (int s = 128; s; s >>= 1){ if (tid < s) rbuf[tid] = fmaxf(rbuf[tid], rbuf[tid+s]); __syncthreads(); }
    mx = rbuf[0]; __syncthreads();
    float sum = 0.f;
    #pragma unroll
    for (int k = 0; k < 8; k++){
        float e = expf(sl[k*256 + tid] - mx);
        sl[k*256 + tid] = e; sum += e;
    }
    rbuf[tid] = sum; __syncthreads();
    for (int s = 128; s; s >>= 1){ if (tid < s) rbuf[tid] += rbuf[tid+s]; __syncthreads(); }
    float inv = 1.f/rbuf[0];
    #pragma unroll
    for (int k = 0; k < 8; k++) g_rcw[base + k*256 + tid] = sl[k*256 + tid]*inv;
}

// ---- fused link update + fwd/bwd: 512 threads, 4 j-cols/thread,
//      2-row batching, unroll 4 (8 rows' loads in flight) + warp_sum4 ----
__global__ void __launch_bounds__(512, 2)
k_link(const float* __restrict__ link_old, const float* __restrict__ prec_old,
       const float* __restrict__ rw_old, float* __restrict__ out){
    __shared__ float wwi_s[TI];
    __shared__ float rwi_s[NR][TI];
    __shared__ float sfwd[TI][NR][17];   // 16 warp-partials + pad
    __shared__ float cfix[TI][NR];       // diag corrections for fwd
    int b = blockIdx.y;
    int i0 = blockIdx.x * TI;
    int tid = threadIdx.x;
    int wrp = tid >> 5, lane = tid & 31;
    float inv = 1.f/g_wcwsum[b];
    float agv = g_ag[b], wgv = g_wg[b];
    float c_alloc = wgv*agv;
    float c_cw = wgv*(1.f-agv)*inv;
    if (tid < TI)
        wwi_s[tid] = c_alloc*g_alloc[b*NN + i0 + tid] + c_cw*g_wcwlog[b*NN + i0 + tid];
    {   // 512 threads load 512 rwi values
        int r = tid >> 7, ii = tid & 127;
        rwi_s[r][ii] = rw_old[(b*NR+r)*NN + i0 + ii];
    }
    int jb = tid * 4;
    float wwj[4], pj[4], rwj[NR][4];
    #pragma unroll
    for (int k = 0; k < 4; k++){
        wwj[k] = c_alloc*g_alloc[b*NN + jb + k] + c_cw*g_wcwlog[b*NN + jb + k];
        pj[k]  = prec_old[b*NN + jb + k];
    }
    #pragma unroll
    for (int r = 0; r < NR; r++)
        #pragma unroll
        for (int k = 0; k < 4; k++) rwj[r][k] = rw_old[(b*NR+r)*NN + jb + k];
    float bwd[NR][4];
    #pragma unroll
    for (int r = 0; r < NR; r++)
        #pragma unroll
        for (int k = 0; k < 4; k++) bwd[r][k] = 0.f;
    __syncthreads();
    const float* Lb = link_old + ((size_t)b*NN + i0)*NN + jb;
    float* Ob = out + OFF_LINK + ((size_t)b*NN + i0)*NN + jb;
    int rsel = ((lane & 1) << 1) | ((lane >> 1) & 1);   // r owned after warp_sum4
    #pragma unroll 4
    for (int ii0 = 0; ii0 < TI; ii0 += 2){
        float4 oA = __ldcs((const float4*)(Lb + (size_t)ii0*NN));
        float4 oB = __ldcs((const float4*)(Lb + (size_t)(ii0+1)*NN));
        float wwiA = wwi_s[ii0],   t1A = 1.f - wwiA;
        float wwiB = wwi_s[ii0+1], t1B = 1.f - wwiB;
        float nvA[4], nvB[4];
        nvA[0] = (t1A - wwj[0])*oA.x + wwiA*pj[0];
        nvA[1] = (t1A - wwj[1])*oA.y + wwiA*pj[1];
        nvA[2] = (t1A - wwj[2])*oA.z + wwiA*pj[2];
        nvA[3] = (t1A - wwj[3])*oA.w + wwiA*pj[3];
        nvB[0] = (t1B - wwj[0])*oB.x + wwiB*pj[0];
        nvB[1] = (t1B - wwj[1])*oB.y + wwiB*pj[1];
        nvB[2] = (t1B - wwj[2])*oB.z + wwiB*pj[2];
        nvB[3] = (t1B - wwj[3])*oB.w + wwiB*pj[3];
        __stcs((float4*)(Ob + (size_t)ii0*NN),     make_float4(nvA[0],nvA[1],nvA[2],nvA[3]));
        __stcs((float4*)(Ob + (size_t)(ii0+1)*NN), make_float4(nvB[0],nvB[1],nvB[2],nvB[3]));
        float fA[NR], fB[NR];
        #pragma unroll
        for (int r = 0; r < NR; r++){
            fA[r] = nvA[0]*rwj[r][0] + nvA[1]*rwj[r][1] + nvA[2]*rwj[r][2] + nvA[3]*rwj[r][3];
            fB[r] = nvB[0]*rwj[r][0] + nvB[1]*rwj[r][1] + nvB[2]*rwj[r][2] + nvB[3]*rwj[r][3];
        }
        float vA = warp_sum4(fA, lane);
        float vB = warp_sum4(fB, lane);
        if (lane < 4){
            sfwd[ii0][rsel][wrp]   = vA;
            sfwd[ii0+1][rsel][wrp] = vB;
        }
        #pragma unroll
        for (int r = 0; r < NR; r++){
            float rwiA = rwi_s[r][ii0], rwiB = rwi_s[r][ii0+1];
            #pragma unroll
            for (int k = 0; k < 4; k++) bwd[r][k] += rwiA*nvA[k] + rwiB*nvB[k];
        }
    }
    // diag fix: 32 threads own the block's 128 diagonal elements
    if (jb >= i0 && jb < i0 + TI){
        #pragma unroll
        for (int k = 0; k < 4; k++){
            int ii = jb - i0 + k;               // row; column jb+k == i0+ii
            float wwi = wwi_s[ii];
            float oldd = Lb[(size_t)ii*NN + k];
            float v = (1.f - wwi - wwj[k])*oldd + wwi*pj[k];
            Ob[(size_t)ii*NN + k] = 0.f;
            #pragma unroll
            for (int r = 0; r < NR; r++){
                bwd[r][k] -= rwi_s[r][ii]*v;
                cfix[ii][r] = v*rwj[r][k];
            }
        }
    }
    __syncthreads();
    {   // fwd reduce: 512 outputs (TI*NR), one per thread
        int ii = tid >> 2, r = tid & 3;
        float s = -cfix[ii][r];
        #pragma unroll
        for (int w = 0; w < 16; w++) s += sfwd[ii][r][w];
        g_fwd[(b*NR+r)*NN + i0 + ii] = s;
    }
    #pragma unroll
    for (int r = 0; r < NR; r++)
        #pragma unroll
        for (int k = 0; k < 4; k++) atomicAdd(&g_bwd[(b*NR+r)*NN + jb + k], bwd[r][k]);
}

// ---- rw_new mix + read vectors (partial over 64-n chunks, atomics into out) ----
__global__ void k_rvrw(float* __restrict__ out){
    __shared__ float tile[64*WC];
    __shared__ float srw[NR*64];
    int b = blockIdx.x >> 5;
    int c = blockIdx.x & 31;
    int tid = threadIdx.x;
    int r = tid >> 6, idx = tid & 63;
    int n0 = c*64, n = n0 + idx;
    float m0r = g_rmraw[b*12 + r*3 + 0];
    float m1r = g_rmraw[b*12 + r*3 + 1];
    float m2r = g_rmraw[b*12 + r*3 + 2];
    float mx = fmaxf(m0r, fmaxf(m1r, m2r));
    float e0 = expf(m0r-mx), e1 = expf(m1r-mx), e2 = expf(m2r-mx);
    float inv = 1.f/(e0+e1+e2);
    int base = (b*NR+r)*NN;
    float rwv = e0*inv*g_bwd[base+n] + e1*inv*g_fwd[base+n] + e2*inv*g_rcw[base+n];
    out[OFF_RW + base + n] = rwv;
    srw[r*64 + idx] = rwv;
    for (int i = tid; i < 64*WC; i += 256)
        tile[i] = out[OFF_MEM + ((size_t)b*NN + n0)*WC + i];
    __syncthreads();
    float acc = 0.f;
    #pragma unroll 8
    for (int i = 0; i < 64; i++) acc += srw[r*64 + i]*tile[i*WC + idx];
    atomicAdd(&out[OFF_RV + b*256 + r*64 + idx], acc);
}

extern "C" void kernel_launch(void* const* d_in, const int* in_sizes, int n_in,
                              void* d_out, int out_size){
    const float* x        = (const float*)d_in[0];
    const float* memory   = (const float*)d_in[1];
    const float* link_old = (const float*)d_in[2];
    const float* prec     = (const float*)d_in[3];
    const float* rw_old   = (const float*)d_in[4];
    const float* ww_old   = (const float*)d_in[5];
    const float* usage0   = (const float*)d_in[6];
    CP cp;
    for (int s = 0; s < 10; s++){
        cp.W[s]    = (const float*)d_in[7 + 2*s];
        cp.bvec[s] = (const float*)d_in[8 + 2*s];
    }
    const float* W_fg = cp.W[6];
    const float* b_fg = cp.bvec[6];
    float* out = (float*)d_out;

    static cudaStream_t s1 = nullptr;
    static cudaEvent_t eF = nullptr, eA = nullptr, e1 = nullptr, e2 = nullptr;
    if (!s1){
        cudaStreamCreateWithFlags(&s1, cudaStreamNonBlocking);
        cudaEventCreateWithFlags(&eF, cudaEventDisableTiming);
        cudaEventCreateWithFlags(&eA, cudaEventDisableTiming);
        cudaEventCreateWithFlags(&e1, cudaEventDisableTiming);
        cudaEventCreateWithFlags(&e2, cudaEventDisableTiming);
    }

    // FORK: side stream joins capture via event before any launch on it.
    cudaEventRecord(eF, 0);
    cudaStreamWaitEvent(s1, eF, 0);

    // main: alloc -> [join e1] -> link(inline ww) -> [join e2] -> rvrw
    // side: ctrl -> wcwlog(+zero) -> (e1) -> [wait eA] -> ww -> memnew -> rcwsm -> (e2)
    k_alloc <<<NB, 1024>>>(usage0, ww_old, rw_old, x, W_fg, b_fg, out);  // main
    cudaEventRecord(eA, 0);

    k_ctrl  <<<59, 256, 0, s1>>>(x, cp);                                 // side
    k_wcwlog<<<NB*8, 256, 0, s1>>>(memory, out);                         // side
    cudaEventRecord(e1, s1);
    cudaStreamWaitEvent(s1, eA, 0);

    cudaStreamWaitEvent(0, e1, 0);
    k_link  <<<dim3(NN/TI, NB), 512>>>(link_old, prec, rw_old, out);     // main (big)

    k_ww    <<<NB*8, 256, 0, s1>>>(prec, out);                           // side
    k_memnew<<<NB*256, 256, 0, s1>>>(memory, out);                       // side
    k_rcwsm <<<NB*NR, 256, 0, s1>>>();                                   // side
    cudaEventRecord(e2, s1);
    cudaStreamWaitEvent(0, e2, 0);

    k_rvrw  <<<NB*32, 256>>>(out);                                       // main
}